// round 1
// baseline (speedup 1.0000x reference)
#include <cuda_runtime.h>

// Problem constants
#define BB 8
#define SS 2048
#define EE 512

// Scratch (allocation-free: __device__ globals)
__device__ float g_q [BB * SS * EE];           // 33.5 MB
__device__ float g_k [BB * SS * EE];
__device__ float g_v [BB * SS * EE];
__device__ float g_ao[BB * SS * EE];
__device__ float g_scores[BB * SS * SS];       // 134 MB
__device__ int   g_mask4;                      // 1 if mask elements are 4-byte

// ---------------------------------------------------------------------------
// Mask dtype probe: numpy bool (1 byte) has ~50% nonzero bytes at every
// offset; int32/float32 encodings of 0/1 have byte offset %4==1 always zero.
// Deterministic for a fixed input.
// ---------------------------------------------------------------------------
__global__ void detect_mask_kernel(const unsigned char* __restrict__ mask) {
    __shared__ int found;
    if (threadIdx.x == 0) found = 0;
    __syncthreads();
    for (int i = threadIdx.x; i < 1024; i += 256) {
        if (mask[i * 4 + 1] != 0) found = 1;
    }
    __syncthreads();
    if (threadIdx.x == 0) g_mask4 = found ? 0 : 1;
}

// ---------------------------------------------------------------------------
// Generic 128x128x16 fp32 GEMM, double-buffered smem, 8x8 per-thread tile.
//   TRANSB=true : C = alpha * A[M,K] * B[N,K]^T   (both row-major, NT)
//   TRANSB=false: C = alpha * A[M,K] * B[K,N]     (NN)
// Optional bias[n] and resid[m,n] added in epilogue. Batched via blockIdx.z
// with element strides sA/sB/sC. Requires M%128==0, N%128==0, K%16==0.
// ---------------------------------------------------------------------------
template <bool TRANSB, bool BIAS, bool RESID>
__global__ void __launch_bounds__(256)
gemm_kernel(const float* __restrict__ A, const float* __restrict__ B,
            float* __restrict__ C,
            int M, int N, int K,
            long long sA, long long sB, long long sC,
            float alpha,
            const float* __restrict__ bias,
            const float* __restrict__ resid) {
    __shared__ float As[2][16][132];   // padded to 132 to reduce store conflicts
    __shared__ float Bs[2][16][132];

    const int bz = blockIdx.z;
    const float* Ab = A + (long long)bz * sA;
    const float* Bb = B + (long long)bz * sB;
    float*       Cb = C + (long long)bz * sC;

    const int m0 = blockIdx.y * 128;
    const int n0 = blockIdx.x * 128;

    const int tid = threadIdx.x;
    const int tx  = tid & 15;   // 0..15 (column group)
    const int ty  = tid >> 4;   // 0..15 (row group)

    // Global-load mapping for K-major tiles (A always; B when TRANSB)
    const int arow = tid >> 2;  // 0..63
    const int acg  = tid & 3;   // 0..3  (4-float column group within BK=16)
    // Global-load mapping for NN B tiles
    const int brow = tid >> 5;  // 0..7
    const int bcg  = tid & 31;  // 0..31

    const int nkt = K >> 4;

    float4 ra0, ra1, rb0, rb1;

    auto fetch = [&](int kt) {
        {
            const float* p = Ab + (long long)(m0 + arow) * K + (kt << 4) + (acg << 2);
            ra0 = *reinterpret_cast<const float4*>(p);
            ra1 = *reinterpret_cast<const float4*>(p + (long long)64 * K);
        }
        if (TRANSB) {
            const float* p = Bb + (long long)(n0 + arow) * K + (kt << 4) + (acg << 2);
            rb0 = *reinterpret_cast<const float4*>(p);
            rb1 = *reinterpret_cast<const float4*>(p + (long long)64 * K);
        } else {
            const float* p = Bb + (long long)((kt << 4) + brow) * N + n0 + (bcg << 2);
            rb0 = *reinterpret_cast<const float4*>(p);
            rb1 = *reinterpret_cast<const float4*>(p + (long long)8 * N);
        }
    };

    auto stage = [&](int buf) {
        const int k4 = acg << 2;
        As[buf][k4 + 0][arow]      = ra0.x;
        As[buf][k4 + 1][arow]      = ra0.y;
        As[buf][k4 + 2][arow]      = ra0.z;
        As[buf][k4 + 3][arow]      = ra0.w;
        As[buf][k4 + 0][arow + 64] = ra1.x;
        As[buf][k4 + 1][arow + 64] = ra1.y;
        As[buf][k4 + 2][arow + 64] = ra1.z;
        As[buf][k4 + 3][arow + 64] = ra1.w;
        if (TRANSB) {
            Bs[buf][k4 + 0][arow]      = rb0.x;
            Bs[buf][k4 + 1][arow]      = rb0.y;
            Bs[buf][k4 + 2][arow]      = rb0.z;
            Bs[buf][k4 + 3][arow]      = rb0.w;
            Bs[buf][k4 + 0][arow + 64] = rb1.x;
            Bs[buf][k4 + 1][arow + 64] = rb1.y;
            Bs[buf][k4 + 2][arow + 64] = rb1.z;
            Bs[buf][k4 + 3][arow + 64] = rb1.w;
        } else {
            *reinterpret_cast<float4*>(&Bs[buf][brow][bcg << 2])     = rb0;
            *reinterpret_cast<float4*>(&Bs[buf][brow + 8][bcg << 2]) = rb1;
        }
    };

    float acc[8][8];
#pragma unroll
    for (int i = 0; i < 8; i++)
#pragma unroll
        for (int j = 0; j < 8; j++) acc[i][j] = 0.f;

    fetch(0);
    stage(0);
    __syncthreads();

    for (int kt = 0; kt < nkt; kt++) {
        const int buf = kt & 1;
        if (kt + 1 < nkt) fetch(kt + 1);
#pragma unroll
        for (int kk = 0; kk < 16; kk++) {
            float4 a0 = *reinterpret_cast<const float4*>(&As[buf][kk][ty << 2]);
            float4 a1 = *reinterpret_cast<const float4*>(&As[buf][kk][(ty << 2) + 64]);
            float4 b0 = *reinterpret_cast<const float4*>(&Bs[buf][kk][tx << 2]);
            float4 b1 = *reinterpret_cast<const float4*>(&Bs[buf][kk][(tx << 2) + 64]);
            float a[8] = {a0.x, a0.y, a0.z, a0.w, a1.x, a1.y, a1.z, a1.w};
            float b[8] = {b0.x, b0.y, b0.z, b0.w, b1.x, b1.y, b1.z, b1.w};
#pragma unroll
            for (int i = 0; i < 8; i++)
#pragma unroll
                for (int j = 0; j < 8; j++)
                    acc[i][j] = fmaf(a[i], b[j], acc[i][j]);
        }
        if (kt + 1 < nkt) stage(buf ^ 1);
        __syncthreads();
    }

#pragma unroll
    for (int qi = 0; qi < 2; qi++) {
#pragma unroll
        for (int i = 0; i < 4; i++) {
            const int row = m0 + qi * 64 + (ty << 2) + i;
            const int ri  = qi * 4 + i;
#pragma unroll
            for (int qj = 0; qj < 2; qj++) {
                const int col = n0 + qj * 64 + (tx << 2);
                const int cj  = qj * 4;
                float4 v;
                v.x = acc[ri][cj + 0] * alpha;
                v.y = acc[ri][cj + 1] * alpha;
                v.z = acc[ri][cj + 2] * alpha;
                v.w = acc[ri][cj + 3] * alpha;
                if (BIAS) {
                    v.x += bias[col + 0];
                    v.y += bias[col + 1];
                    v.z += bias[col + 2];
                    v.w += bias[col + 3];
                }
                if (RESID) {
                    const float4 r =
                        *reinterpret_cast<const float4*>(&resid[(long long)row * N + col]);
                    v.x += r.x; v.y += r.y; v.z += r.z; v.w += r.w;
                }
                *reinterpret_cast<float4*>(&Cb[(long long)row * N + col]) = v;
            }
        }
    }
}

// ---------------------------------------------------------------------------
// Fused mask + row softmax over scores [B*S, S], in place.
// x = mask ? -1e9 : x; softmax(x). All-masked rows -> uniform (matches ref).
// ---------------------------------------------------------------------------
__global__ void __launch_bounds__(256)
softmax_mask_kernel(float* __restrict__ scores, const void* __restrict__ mask) {
    const long long row   = blockIdx.x;
    float* sr             = scores + row * SS;
    const long long mbase = row * SS;
    const int tid         = threadIdx.x;
    const int is4         = g_mask4;

    float vals[8];
    float mx = -3.0e38f;
#pragma unroll
    for (int i = 0; i < 8; i++) {
        const int c = tid + (i << 8);
        float x = sr[c];
        bool m;
        if (is4)
            m = reinterpret_cast<const unsigned int*>(mask)[mbase + c] != 0u;
        else
            m = reinterpret_cast<const unsigned char*>(mask)[mbase + c] != 0;
        x = m ? -1e9f : x;
        vals[i] = x;
        mx = fmaxf(mx, x);
    }

    __shared__ float sred[8];
#pragma unroll
    for (int o = 16; o > 0; o >>= 1) mx = fmaxf(mx, __shfl_xor_sync(0xffffffffu, mx, o));
    if ((tid & 31) == 0) sred[tid >> 5] = mx;
    __syncthreads();
    float bm = sred[0];
#pragma unroll
    for (int w = 1; w < 8; w++) bm = fmaxf(bm, sred[w]);

    float sum = 0.f;
#pragma unroll
    for (int i = 0; i < 8; i++) {
        const float e = __expf(vals[i] - bm);
        vals[i] = e;
        sum += e;
    }
#pragma unroll
    for (int o = 16; o > 0; o >>= 1) sum += __shfl_xor_sync(0xffffffffu, sum, o);
    __shared__ float ssum[8];
    if ((tid & 31) == 0) ssum[tid >> 5] = sum;
    __syncthreads();
    float ts = 0.f;
#pragma unroll
    for (int w = 0; w < 8; w++) ts += ssum[w];

    const float inv = 1.0f / ts;
#pragma unroll
    for (int i = 0; i < 8; i++) {
        const int c = tid + (i << 8);
        sr[c] = vals[i] * inv;
    }
}

// ---------------------------------------------------------------------------
// kernel_launch: graph-capturable, allocation-free.
// Inputs: Q, K, pad_mask, Wq, Wk, Wv, Wp, bp
// ---------------------------------------------------------------------------
extern "C" void kernel_launch(void* const* d_in, const int* in_sizes, int n_in,
                              void* d_out, int out_size) {
    const float* Q    = (const float*)d_in[0];
    const float* Kin  = (const float*)d_in[1];
    const void*  mask = (const void*)d_in[2];
    const float* Wq   = (const float*)d_in[3];
    const float* Wk   = (const float*)d_in[4];
    const float* Wv   = (const float*)d_in[5];
    const float* Wp   = (const float*)d_in[6];
    const float* bp   = (const float*)d_in[7];
    float* out        = (float*)d_out;

    float *q, *k, *v, *ao, *sc;
    cudaGetSymbolAddress((void**)&q,  g_q);
    cudaGetSymbolAddress((void**)&k,  g_k);
    cudaGetSymbolAddress((void**)&v,  g_v);
    cudaGetSymbolAddress((void**)&ao, g_ao);
    cudaGetSymbolAddress((void**)&sc, g_scores);

    const float scale = 0.04419417382415922f;  // 512^-0.5
    const long long sQKV = (long long)SS * EE;
    const long long sSC  = (long long)SS * SS;
    dim3 blk(256);

    // Input projections: q = Q Wq^T, k = K Wk^T, v = K Wv^T
    dim3 gproj(EE / 128, (BB * SS) / 128, 1);
    gemm_kernel<true, false, false><<<gproj, blk>>>(Q,   Wq, q, BB * SS, EE, EE, 0, 0, 0, 1.f, nullptr, nullptr);
    gemm_kernel<true, false, false><<<gproj, blk>>>(Kin, Wk, k, BB * SS, EE, EE, 0, 0, 0, 1.f, nullptr, nullptr);
    gemm_kernel<true, false, false><<<gproj, blk>>>(Kin, Wv, v, BB * SS, EE, EE, 0, 0, 0, 1.f, nullptr, nullptr);

    // Mask dtype probe
    detect_mask_kernel<<<1, 256>>>((const unsigned char*)mask);

    // scores[b] = scale * q[b] k[b]^T
    dim3 gsc(SS / 128, SS / 128, BB);
    gemm_kernel<true, false, false><<<gsc, blk>>>(q, k, sc, SS, SS, EE, sQKV, sQKV, sSC, scale, nullptr, nullptr);

    // mask + softmax in place
    softmax_mask_kernel<<<BB * SS, 256>>>(sc, mask);

    // attn_out[b] = attn[b] v[b]   (NN)
    dim3 gav(EE / 128, SS / 128, BB);
    gemm_kernel<false, false, false><<<gav, blk>>>(sc, v, ao, SS, EE, SS, sSC, sQKV, sQKV, 1.f, nullptr, nullptr);

    // out = attn_out Wp^T + bp + q   (residual on projected q)
    gemm_kernel<true, true, true><<<gproj, blk>>>(ao, Wp, out, BB * SS, EE, EE, 0, 0, 0, 1.f, bp, q);
}

// round 3
// speedup vs baseline: 2.9084x; 2.9084x over previous
#include <cuda_runtime.h>
#include <cuda_bf16.h>
#include <cstdint>

#define BB 8
#define SS 2048
#define EE 512
#define MTOT (BB * SS)

// ---------------------------------------------------------------------------
// Scratch (__device__ globals; no allocation anywhere)
// ---------------------------------------------------------------------------
__device__ __nv_bfloat16 g_Qhi[(size_t)MTOT * EE], g_Qlo[(size_t)MTOT * EE];
__device__ __nv_bfloat16 g_Khi[(size_t)MTOT * EE], g_Klo[(size_t)MTOT * EE];
__device__ __nv_bfloat16 g_Wqhi[EE * EE], g_Wqlo[EE * EE];
__device__ __nv_bfloat16 g_Wkhi[EE * EE], g_Wklo[EE * EE];
__device__ __nv_bfloat16 g_Wvhi[EE * EE], g_Wvlo[EE * EE];
__device__ __nv_bfloat16 g_Wphi[EE * EE], g_Wplo[EE * EE];
__device__ float         g_qf [(size_t)MTOT * EE];
__device__ __nv_bfloat16 g_qhi[(size_t)MTOT * EE], g_qlo[(size_t)MTOT * EE];
__device__ __nv_bfloat16 g_khi[(size_t)MTOT * EE], g_klo[(size_t)MTOT * EE];
__device__ __nv_bfloat16 g_vThi[(size_t)BB * EE * SS], g_vTlo[(size_t)BB * EE * SS];
__device__ float         g_scores[(size_t)BB * SS * SS];
__device__ __nv_bfloat16 g_phi[(size_t)BB * SS * SS], g_plo[(size_t)BB * SS * SS];
__device__ __nv_bfloat16 g_aohi[(size_t)MTOT * EE], g_aolo[(size_t)MTOT * EE];
__device__ int           g_mask4;

// ---------------------------------------------------------------------------
// Helpers (baseline PTX only: sm_80-era instructions, legal at .target sm_103)
// ---------------------------------------------------------------------------
__device__ __forceinline__ uint32_t smem_u32(const void* p) {
    uint32_t a;
    asm("{ .reg .u64 t; cvta.to.shared.u64 t, %1; cvt.u32.u64 %0, t; }"
        : "=r"(a) : "l"(p));
    return a;
}
__device__ __forceinline__ void cpasync16(uint32_t dst, const void* src) {
    asm volatile("cp.async.cg.shared.global [%0], [%1], 16;"
                 :: "r"(dst), "l"(src) : "memory");
}
#define CP_COMMIT() asm volatile("cp.async.commit_group;" ::: "memory")
#define CP_WAIT1()  asm volatile("cp.async.wait_group 1;" ::: "memory")
#define CP_WAIT0()  asm volatile("cp.async.wait_group 0;" ::: "memory")

__device__ __forceinline__ void ldsm4(uint32_t* r, uint32_t addr) {
    asm volatile("ldmatrix.sync.aligned.m8n8.x4.shared.b16 {%0,%1,%2,%3}, [%4];"
                 : "=r"(r[0]), "=r"(r[1]), "=r"(r[2]), "=r"(r[3]) : "r"(addr));
}
__device__ __forceinline__ void mma_bf16(float* d, const uint32_t* a, const uint32_t* b) {
    asm volatile(
        "mma.sync.aligned.m16n8k16.row.col.f32.bf16.bf16.f32 "
        "{%0,%1,%2,%3}, {%4,%5,%6,%7}, {%8,%9}, {%0,%1,%2,%3};"
        : "+f"(d[0]), "+f"(d[1]), "+f"(d[2]), "+f"(d[3])
        : "r"(a[0]), "r"(a[1]), "r"(a[2]), "r"(a[3]), "r"(b[0]), "r"(b[1]));
}

// SMEM geometry: 4 tiles (Ahi, Alo, Bhi, Blo), each 128 rows x 32 bf16,
// row pitch 80 B (64 B data + 16 B pad -> conflict-free ldmatrix).
#define PITCH    80
#define TILE_B   (128 * PITCH)          // 10240
#define STAGE_B  (4 * TILE_B)           // 40960
#define SMEM_B   (2 * STAGE_B)          // 81920

// ---------------------------------------------------------------------------
// HMMA NT GEMM: C[M,N] = alpha * A[M,K] * B[N,K]^T via bf16 hi/lo split
// (hi*hi + hi*lo + lo*hi), fp32 register accumulation.
// BM=BN=128, BK=32, 256 threads, warp tile 32x64 (warps: 4 m-groups x 2 n).
// Requires M%128==0, N%128==0, K%32==0, nkt>=2.
// ---------------------------------------------------------------------------
template <bool BIAS, bool RESID, bool WF32, bool WSPLIT>
__global__ void __launch_bounds__(256, 1)
hmma_gemm(const __nv_bfloat16* __restrict__ Ahi, const __nv_bfloat16* __restrict__ Alo,
          const __nv_bfloat16* __restrict__ Bhi, const __nv_bfloat16* __restrict__ Blo,
          float* __restrict__ C, __nv_bfloat16* __restrict__ Chi,
          __nv_bfloat16* __restrict__ Clo,
          int M, int N, int K,
          long long sA, long long sB, long long sC,
          float alpha, const float* __restrict__ bias, const float* __restrict__ resid) {
    extern __shared__ __align__(128) char smem[];
    const uint32_t sb = smem_u32(smem);

    const int tid  = threadIdx.x;
    const int wid  = tid >> 5;
    const int lane = tid & 31;
    const int bz   = blockIdx.z;
    const int m0   = blockIdx.y * 128;
    const int n0   = blockIdx.x * 128;

    const __nv_bfloat16* Ah = Ahi + (long long)bz * sA;
    const __nv_bfloat16* Al = Alo + (long long)bz * sA;
    const __nv_bfloat16* Bh = Bhi + (long long)bz * sB;
    const __nv_bfloat16* Bl = Blo + (long long)bz * sB;

    const int nkt = K >> 5;

    auto FETCH = [&](int kt, int st) {
        const uint32_t base = sb + st * STAGE_B;
#pragma unroll
        for (int t = 0; t < 2; t++) {
            const int c   = tid + t * 256;       // 0..511
            const int row = c >> 2;              // 0..127
            const int cp  = c & 3;               // 16B chunk within 64B row
            const uint32_t doff = row * PITCH + cp * 16;
            const long long ga = (long long)(m0 + row) * K + (kt << 5) + cp * 8;
            const long long gb = (long long)(n0 + row) * K + (kt << 5) + cp * 8;
            cpasync16(base + doff,              Ah + ga);
            cpasync16(base + TILE_B + doff,     Al + ga);
            cpasync16(base + 2 * TILE_B + doff, Bh + gb);
            cpasync16(base + 3 * TILE_B + doff, Bl + gb);
        }
        CP_COMMIT();
    };

    float acc[2][8][4];
#pragma unroll
    for (int mt = 0; mt < 2; mt++)
#pragma unroll
        for (int nt = 0; nt < 8; nt++)
#pragma unroll
            for (int j = 0; j < 4; j++) acc[mt][nt][j] = 0.f;

    const int wm = (wid & 3) * 32;   // warp m offset within block
    const int wn = (wid >> 2) * 64;  // warp n offset within block
    const int i8 = lane & 7;
    // ldmatrix lane-address offsets (bytes), per fragment mapping:
    // A x4: r0=(m0-7,k0-7) r1=(m8-15,k0-7) r2=(m0-7,k8-15) r3=(m8-15,k8-15)
    const uint32_t a_off = (uint32_t)(i8 + ((lane >> 3) & 1) * 8) * PITCH + (lane >> 4) * 16;
    // B x4: r0=(n0-7,k0-7) r1=(n0-7,k8-15) r2=(n8-15,k0-7) r3=(n8-15,k8-15)
    const uint32_t b_off = (uint32_t)(i8 + ((lane >> 4) & 1) * 8) * PITCH + ((lane >> 3) & 1) * 16;

    auto COMPUTE = [&](int st) {
        const uint32_t base = sb + st * STAGE_B;
        const uint32_t aAh = base + (uint32_t)wm * PITCH + a_off;
        const uint32_t aAl = aAh + TILE_B;
        const uint32_t aBh = base + 2 * TILE_B + (uint32_t)wn * PITCH + b_off;
        const uint32_t aBl = aBh + TILE_B;
#pragma unroll
        for (int ks = 0; ks < 2; ks++) {
            uint32_t ah[2][4], al[2][4], bh[4][4], bl[4][4];
#pragma unroll
            for (int mt = 0; mt < 2; mt++) {
                ldsm4(ah[mt], aAh + mt * 16 * PITCH + ks * 32);
                ldsm4(al[mt], aAl + mt * 16 * PITCH + ks * 32);
            }
#pragma unroll
            for (int nt = 0; nt < 4; nt++) {
                ldsm4(bh[nt], aBh + nt * 16 * PITCH + ks * 32);
                ldsm4(bl[nt], aBl + nt * 16 * PITCH + ks * 32);
            }
            // combo 1: hi*hi
#pragma unroll
            for (int mt = 0; mt < 2; mt++)
#pragma unroll
                for (int nt = 0; nt < 8; nt++)
                    mma_bf16(acc[mt][nt], ah[mt], &bh[nt >> 1][(nt & 1) * 2]);
            // combo 2: hi*lo
#pragma unroll
            for (int mt = 0; mt < 2; mt++)
#pragma unroll
                for (int nt = 0; nt < 8; nt++)
                    mma_bf16(acc[mt][nt], ah[mt], &bl[nt >> 1][(nt & 1) * 2]);
            // combo 3: lo*hi
#pragma unroll
            for (int mt = 0; mt < 2; mt++)
#pragma unroll
                for (int nt = 0; nt < 8; nt++)
                    mma_bf16(acc[mt][nt], al[mt], &bh[nt >> 1][(nt & 1) * 2]);
        }
    };

    FETCH(0, 0);
    FETCH(1, 1);

    for (int kt = 0; kt < nkt; kt++) {
        const int st = kt & 1;
        if (kt + 1 < nkt) { CP_WAIT1(); } else { CP_WAIT0(); }
        __syncthreads();
        COMPUTE(st);
        if (kt + 2 < nkt) {
            __syncthreads();
            FETCH(kt + 2, st);
        }
    }

    // Epilogue
    float* Cb = WF32 ? (C + (long long)bz * sC) : nullptr;
    __nv_bfloat16* Hh = WSPLIT ? (Chi + (long long)bz * sC) : nullptr;
    __nv_bfloat16* Hl = WSPLIT ? (Clo + (long long)bz * sC) : nullptr;
    const float* Rb = RESID ? (resid + (long long)bz * sC) : nullptr;

    const int r0 = lane >> 2;
    const int c0 = (lane & 3) * 2;
#pragma unroll
    for (int mt = 0; mt < 2; mt++) {
#pragma unroll
        for (int nt = 0; nt < 8; nt++) {
            const int col = n0 + wn + nt * 8 + c0;
#pragma unroll
            for (int h = 0; h < 2; h++) {
                const long long row = m0 + wm + mt * 16 + r0 + h * 8;
                float v0 = acc[mt][nt][h * 2 + 0] * alpha;
                float v1 = acc[mt][nt][h * 2 + 1] * alpha;
                if (BIAS)  { v0 += bias[col]; v1 += bias[col + 1]; }
                if (RESID) {
                    v0 += Rb[row * N + col];
                    v1 += Rb[row * N + col + 1];
                }
                if (WF32) {
                    float2 o = {v0, v1};
                    *reinterpret_cast<float2*>(&Cb[row * N + col]) = o;
                }
                if (WSPLIT) {
                    __nv_bfloat16 h0 = __float2bfloat16(v0);
                    __nv_bfloat16 h1 = __float2bfloat16(v1);
                    __nv_bfloat162 hp; hp.x = h0; hp.y = h1;
                    __nv_bfloat162 lp;
                    lp.x = __float2bfloat16(v0 - __bfloat162float(h0));
                    lp.y = __float2bfloat16(v1 - __bfloat162float(h1));
                    *reinterpret_cast<__nv_bfloat162*>(&Hh[row * N + col]) = hp;
                    *reinterpret_cast<__nv_bfloat162*>(&Hl[row * N + col]) = lp;
                }
            }
        }
    }
}

// ---------------------------------------------------------------------------
// fp32 -> bf16 hi/lo split (vectorized by 4)
// ---------------------------------------------------------------------------
__global__ void __launch_bounds__(256)
split_kernel(const float* __restrict__ x, __nv_bfloat16* __restrict__ hi,
             __nv_bfloat16* __restrict__ lo, int n4) {
    const int i = blockIdx.x * 256 + threadIdx.x;
    if (i >= n4) return;
    const float4 v = reinterpret_cast<const float4*>(x)[i];
    __nv_bfloat16 h0 = __float2bfloat16(v.x), h1 = __float2bfloat16(v.y);
    __nv_bfloat16 h2 = __float2bfloat16(v.z), h3 = __float2bfloat16(v.w);
    __nv_bfloat162 hp0; hp0.x = h0; hp0.y = h1;
    __nv_bfloat162 hp1; hp1.x = h2; hp1.y = h3;
    __nv_bfloat162 lp0, lp1;
    lp0.x = __float2bfloat16(v.x - __bfloat162float(h0));
    lp0.y = __float2bfloat16(v.y - __bfloat162float(h1));
    lp1.x = __float2bfloat16(v.z - __bfloat162float(h2));
    lp1.y = __float2bfloat16(v.w - __bfloat162float(h3));
    reinterpret_cast<__nv_bfloat162*>(hi)[2 * i]     = hp0;
    reinterpret_cast<__nv_bfloat162*>(hi)[2 * i + 1] = hp1;
    reinterpret_cast<__nv_bfloat162*>(lo)[2 * i]     = lp0;
    reinterpret_cast<__nv_bfloat162*>(lo)[2 * i + 1] = lp1;
}

// ---------------------------------------------------------------------------
// Mask dtype probe (bool vs 4-byte): byte offset %4==1 nonzero => 1-byte bool
// ---------------------------------------------------------------------------
__global__ void detect_mask_kernel(const unsigned char* __restrict__ mask) {
    __shared__ int found;
    if (threadIdx.x == 0) found = 0;
    __syncthreads();
    for (int i = threadIdx.x; i < 1024; i += 256)
        if (mask[i * 4 + 1] != 0) found = 1;
    __syncthreads();
    if (threadIdx.x == 0) g_mask4 = found ? 0 : 1;
}

// ---------------------------------------------------------------------------
// Mask + softmax: fp32 scores -> bf16 hi/lo probabilities
// ---------------------------------------------------------------------------
__global__ void __launch_bounds__(256)
softmax_mask_kernel(const float* __restrict__ scores, const void* __restrict__ mask,
                    __nv_bfloat16* __restrict__ phi, __nv_bfloat16* __restrict__ plo) {
    const long long row = blockIdx.x;
    const float* sr = scores + row * SS;
    const long long mbase = row * SS;
    const int tid = threadIdx.x;
    const int is4 = g_mask4;

    float vals[8];
    float mx = -3.0e38f;
#pragma unroll
    for (int i = 0; i < 8; i++) {
        const int c = tid + (i << 8);
        float x = sr[c];
        bool m;
        if (is4) m = reinterpret_cast<const unsigned int*>(mask)[mbase + c] != 0u;
        else     m = reinterpret_cast<const unsigned char*>(mask)[mbase + c] != 0;
        x = m ? -1e9f : x;
        vals[i] = x;
        mx = fmaxf(mx, x);
    }
    __shared__ float sred[8];
#pragma unroll
    for (int o = 16; o > 0; o >>= 1) mx = fmaxf(mx, __shfl_xor_sync(0xffffffffu, mx, o));
    if ((tid & 31) == 0) sred[tid >> 5] = mx;
    __syncthreads();
    float bm = sred[0];
#pragma unroll
    for (int w = 1; w < 8; w++) bm = fmaxf(bm, sred[w]);

    float sum = 0.f;
#pragma unroll
    for (int i = 0; i < 8; i++) {
        const float e = __expf(vals[i] - bm);
        vals[i] = e;
        sum += e;
    }
#pragma unroll
    for (int o = 16; o > 0; o >>= 1) sum += __shfl_xor_sync(0xffffffffu, sum, o);
    __shared__ float ssum[8];
    if ((tid & 31) == 0) ssum[tid >> 5] = sum;
    __syncthreads();
    float ts = 0.f;
#pragma unroll
    for (int w = 0; w < 8; w++) ts += ssum[w];

    const float inv = 1.0f / ts;
#pragma unroll
    for (int i = 0; i < 8; i++) {
        const int c = tid + (i << 8);
        const float p = vals[i] * inv;
        const __nv_bfloat16 h = __float2bfloat16(p);
        phi[mbase + c] = h;
        plo[mbase + c] = __float2bfloat16(p - __bfloat162float(h));
    }
}

// ---------------------------------------------------------------------------
// kernel_launch
// ---------------------------------------------------------------------------
extern "C" void kernel_launch(void* const* d_in, const int* in_sizes, int n_in,
                              void* d_out, int out_size) {
    const float* Q    = (const float*)d_in[0];
    const float* Kin  = (const float*)d_in[1];
    const void*  mask = (const void*)d_in[2];
    const float* Wq   = (const float*)d_in[3];
    const float* Wk   = (const float*)d_in[4];
    const float* Wv   = (const float*)d_in[5];
    const float* Wp   = (const float*)d_in[6];
    const float* bp   = (const float*)d_in[7];
    float* out        = (float*)d_out;

    __nv_bfloat16 *Qhi, *Qlo, *Khi, *Klo, *Wqhi, *Wqlo, *Wkhi, *Wklo, *Wvhi, *Wvlo, *Wphi2, *Wplo2;
    __nv_bfloat16 *qhi, *qlo, *khi, *klo, *vThi, *vTlo, *phi, *plo, *aohi, *aolo;
    float *qf, *sc;
    cudaGetSymbolAddress((void**)&Qhi, g_Qhi);   cudaGetSymbolAddress((void**)&Qlo, g_Qlo);
    cudaGetSymbolAddress((void**)&Khi, g_Khi);   cudaGetSymbolAddress((void**)&Klo, g_Klo);
    cudaGetSymbolAddress((void**)&Wqhi, g_Wqhi); cudaGetSymbolAddress((void**)&Wqlo, g_Wqlo);
    cudaGetSymbolAddress((void**)&Wkhi, g_Wkhi); cudaGetSymbolAddress((void**)&Wklo, g_Wklo);
    cudaGetSymbolAddress((void**)&Wvhi, g_Wvhi); cudaGetSymbolAddress((void**)&Wvlo, g_Wvlo);
    cudaGetSymbolAddress((void**)&Wphi2, g_Wphi); cudaGetSymbolAddress((void**)&Wplo2, g_Wplo);
    cudaGetSymbolAddress((void**)&qf, g_qf);
    cudaGetSymbolAddress((void**)&qhi, g_qhi);   cudaGetSymbolAddress((void**)&qlo, g_qlo);
    cudaGetSymbolAddress((void**)&khi, g_khi);   cudaGetSymbolAddress((void**)&klo, g_klo);
    cudaGetSymbolAddress((void**)&vThi, g_vThi); cudaGetSymbolAddress((void**)&vTlo, g_vTlo);
    cudaGetSymbolAddress((void**)&sc, g_scores);
    cudaGetSymbolAddress((void**)&phi, g_phi);   cudaGetSymbolAddress((void**)&plo, g_plo);
    cudaGetSymbolAddress((void**)&aohi, g_aohi); cudaGetSymbolAddress((void**)&aolo, g_aolo);

    cudaFuncSetAttribute(hmma_gemm<false, false, false, true>,
                         cudaFuncAttributeMaxDynamicSharedMemorySize, SMEM_B);
    cudaFuncSetAttribute(hmma_gemm<false, false, true, true>,
                         cudaFuncAttributeMaxDynamicSharedMemorySize, SMEM_B);
    cudaFuncSetAttribute(hmma_gemm<false, false, true, false>,
                         cudaFuncAttributeMaxDynamicSharedMemorySize, SMEM_B);
    cudaFuncSetAttribute(hmma_gemm<true, true, true, false>,
                         cudaFuncAttributeMaxDynamicSharedMemorySize, SMEM_B);

    const float scale = 0.04419417382415922f;  // 512^-0.5
    const long long sQKV = (long long)SS * EE;
    const long long sSC  = (long long)SS * SS;
    dim3 blk(256);

    // 1) splits
    {
        const int nQ4 = MTOT * EE / 4, nW4 = EE * EE / 4;
        split_kernel<<<(nQ4 + 255) / 256, blk>>>(Q,   Qhi, Qlo, nQ4);
        split_kernel<<<(nQ4 + 255) / 256, blk>>>(Kin, Khi, Klo, nQ4);
        split_kernel<<<(nW4 + 255) / 256, blk>>>(Wq, Wqhi, Wqlo, nW4);
        split_kernel<<<(nW4 + 255) / 256, blk>>>(Wk, Wkhi, Wklo, nW4);
        split_kernel<<<(nW4 + 255) / 256, blk>>>(Wv, Wvhi, Wvlo, nW4);
        split_kernel<<<(nW4 + 255) / 256, blk>>>(Wp, Wphi2, Wplo2, nW4);
    }
    detect_mask_kernel<<<1, 256>>>((const unsigned char*)mask);

    // 2) q = Q Wq^T (fp32 + split)
    hmma_gemm<false, false, true, true><<<dim3(EE / 128, MTOT / 128, 1), blk, SMEM_B>>>(
        Qhi, Qlo, Wqhi, Wqlo, qf, qhi, qlo, MTOT, EE, EE, 0, 0, 0, 1.f, nullptr, nullptr);
    // 3) k = K Wk^T (split)
    hmma_gemm<false, false, false, true><<<dim3(EE / 128, MTOT / 128, 1), blk, SMEM_B>>>(
        Khi, Klo, Wkhi, Wklo, nullptr, khi, klo, MTOT, EE, EE, 0, 0, 0, 1.f, nullptr, nullptr);
    // 4) vT[b] = Wv K[b]^T  (M=E, N=S per batch; split)
    hmma_gemm<false, false, false, true><<<dim3(SS / 128, EE / 128, BB), blk, SMEM_B>>>(
        Wvhi, Wvlo, Khi, Klo, nullptr, vThi, vTlo, EE, SS, EE,
        0, sQKV, (long long)EE * SS, 1.f, nullptr, nullptr);
    // 5) scores[b] = scale * q[b] k[b]^T  (fp32)
    hmma_gemm<false, false, true, false><<<dim3(SS / 128, SS / 128, BB), blk, SMEM_B>>>(
        qhi, qlo, khi, klo, sc, nullptr, nullptr, SS, SS, EE,
        sQKV, sQKV, sSC, scale, nullptr, nullptr);
    // 6) mask + softmax -> probs split
    softmax_mask_kernel<<<BB * SS, blk>>>(sc, mask, phi, plo);
    // 7) ao[b] = probs[b] vT[b]^T  (split)
    hmma_gemm<false, false, false, true><<<dim3(EE / 128, SS / 128, BB), blk, SMEM_B>>>(
        phi, plo, vThi, vTlo, nullptr, aohi, aolo, SS, EE, SS,
        sSC, (long long)EE * SS, sQKV, 1.f, nullptr, nullptr);
    // 8) out = ao Wp^T + bp + q  (fp32, bias + residual)
    hmma_gemm<true, true, true, false><<<dim3(EE / 128, MTOT / 128, 1), blk, SMEM_B>>>(
        aohi, aolo, Wphi2, Wplo2, out, nullptr, nullptr, MTOT, EE, EE,
        0, 0, 0, 1.f, bp, qf);
}

// round 4
// speedup vs baseline: 4.3143x; 1.4834x over previous
#include <cuda_runtime.h>
#include <cuda_bf16.h>
#include <cstdint>

#define BB 8
#define SS 2048
#define EE 512
#define MTOT (BB * SS)

// ---------------------------------------------------------------------------
// Scratch (__device__ globals; no allocation anywhere)
// ---------------------------------------------------------------------------
__device__ __nv_bfloat16 g_Qhi[(size_t)MTOT * EE], g_Qlo[(size_t)MTOT * EE];
__device__ __nv_bfloat16 g_Khi[(size_t)MTOT * EE], g_Klo[(size_t)MTOT * EE];
__device__ __nv_bfloat16 g_Wqhi[EE * EE], g_Wqlo[EE * EE];
__device__ __nv_bfloat16 g_Wkhi[EE * EE], g_Wklo[EE * EE];
__device__ __nv_bfloat16 g_Wvhi[EE * EE], g_Wvlo[EE * EE];
__device__ __nv_bfloat16 g_Wphi[EE * EE], g_Wplo[EE * EE];
__device__ float         g_qf [(size_t)MTOT * EE];
__device__ __nv_bfloat16 g_qhi[(size_t)MTOT * EE];
__device__ __nv_bfloat16 g_khi[(size_t)MTOT * EE], g_klo[(size_t)MTOT * EE];
__device__ __nv_bfloat16 g_vThi[(size_t)BB * EE * SS], g_vTlo[(size_t)BB * EE * SS];
__device__ float         g_scores[(size_t)BB * SS * SS];
__device__ __nv_bfloat16 g_phi[(size_t)BB * SS * SS];
__device__ __nv_bfloat16 g_aohi[(size_t)MTOT * EE];
__device__ int           g_mask4;

// ---------------------------------------------------------------------------
// Helpers (baseline PTX only; legal at .target sm_103)
// ---------------------------------------------------------------------------
__device__ __forceinline__ uint32_t smem_u32(const void* p) {
    uint32_t a;
    asm("{ .reg .u64 t; cvta.to.shared.u64 t, %1; cvt.u32.u64 %0, t; }"
        : "=r"(a) : "l"(p));
    return a;
}
__device__ __forceinline__ void cpasync16(uint32_t dst, const void* src) {
    asm volatile("cp.async.cg.shared.global [%0], [%1], 16;"
                 :: "r"(dst), "l"(src) : "memory");
}
#define CP_COMMIT() asm volatile("cp.async.commit_group;" ::: "memory")
#define CP_WAIT1()  asm volatile("cp.async.wait_group 1;" ::: "memory")
#define CP_WAIT0()  asm volatile("cp.async.wait_group 0;" ::: "memory")

__device__ __forceinline__ void ldsm4(uint32_t* r, uint32_t addr) {
    asm volatile("ldmatrix.sync.aligned.m8n8.x4.shared.b16 {%0,%1,%2,%3}, [%4];"
                 : "=r"(r[0]), "=r"(r[1]), "=r"(r[2]), "=r"(r[3]) : "r"(addr));
}
__device__ __forceinline__ void mma_bf16(float* d, const uint32_t* a, const uint32_t* b) {
    asm volatile(
        "mma.sync.aligned.m16n8k16.row.col.f32.bf16.bf16.f32 "
        "{%0,%1,%2,%3}, {%4,%5,%6,%7}, {%8,%9}, {%0,%1,%2,%3};"
        : "+f"(d[0]), "+f"(d[1]), "+f"(d[2]), "+f"(d[3])
        : "r"(a[0]), "r"(a[1]), "r"(a[2]), "r"(a[3]), "r"(b[0]), "r"(b[1]));
}

// SMEM tile: 128 rows x 32 bf16, pitch 80 B (64 data + 16 pad, conflict-free)
#define PITCH    80
#define TILE_B   (128 * PITCH)          // 10240
#define STAGES   3

// ---------------------------------------------------------------------------
// HMMA NT GEMM: C[M,N] = alpha * A[M,K] * B[N,K]^T, bf16 split, fp32 acc.
// NPROD=3: Ah*Bh + Ah*Bl + Al*Bh (needs A-lo).  NPROD=2: Ah*Bh + Ah*Bl.
// BM=BN=128, BK=32, 256 threads, warp tile 32x64. 3-stage cp.async pipeline,
// single __syncthreads per K-iter. Requires M%128==0, N%128==0, K%32==0.
// ---------------------------------------------------------------------------
template <int NPROD, bool BIAS, bool RESID, bool WF32, bool WHI, bool WLO>
__global__ void __launch_bounds__(256, 1)
hmma_gemm(const __nv_bfloat16* __restrict__ Ahi, const __nv_bfloat16* __restrict__ Alo,
          const __nv_bfloat16* __restrict__ Bhi, const __nv_bfloat16* __restrict__ Blo,
          float* __restrict__ C, __nv_bfloat16* __restrict__ Chi,
          __nv_bfloat16* __restrict__ Clo,
          int M, int N, int K,
          long long sA, long long sB, long long sC,
          float alpha, const float* __restrict__ bias, const float* __restrict__ resid) {
    constexpr int NT      = (NPROD == 3) ? 4 : 3;   // tiles per stage
    constexpr int STAGE_B = NT * TILE_B;
    constexpr uint32_t OFF_AL = TILE_B;                            // (3-prod only)
    constexpr uint32_t OFF_BH = (NPROD == 3) ? 2u * TILE_B : TILE_B;
    constexpr uint32_t OFF_BL = OFF_BH + TILE_B;

    extern __shared__ __align__(128) char smem[];
    const uint32_t sb = smem_u32(smem);

    const int tid  = threadIdx.x;
    const int wid  = tid >> 5;
    const int lane = tid & 31;
    const int bz   = blockIdx.z;
    const int m0   = blockIdx.y * 128;
    const int n0   = blockIdx.x * 128;

    const __nv_bfloat16* Ah = Ahi + (long long)bz * sA;
    const __nv_bfloat16* Al = (NPROD == 3) ? (Alo + (long long)bz * sA) : nullptr;
    const __nv_bfloat16* Bh = Bhi + (long long)bz * sB;
    const __nv_bfloat16* Bl = Blo + (long long)bz * sB;

    const int nkt = K >> 5;

    auto FETCH = [&](int kt, int st) {
        const uint32_t base = sb + (uint32_t)st * STAGE_B;
#pragma unroll
        for (int t = 0; t < 2; t++) {
            const int c   = tid + t * 256;       // 0..511
            const int row = c >> 2;              // 0..127
            const int cp  = c & 3;               // 16B chunk within 64B row
            const uint32_t doff = row * PITCH + cp * 16;
            const long long ga = (long long)(m0 + row) * K + (kt << 5) + cp * 8;
            const long long gb = (long long)(n0 + row) * K + (kt << 5) + cp * 8;
            cpasync16(base + doff,          Ah + ga);
            if (NPROD == 3) cpasync16(base + OFF_AL + doff, Al + ga);
            cpasync16(base + OFF_BH + doff, Bh + gb);
            cpasync16(base + OFF_BL + doff, Bl + gb);
        }
        CP_COMMIT();
    };

    float acc[2][8][4];
#pragma unroll
    for (int mt = 0; mt < 2; mt++)
#pragma unroll
        for (int nt = 0; nt < 8; nt++)
#pragma unroll
            for (int j = 0; j < 4; j++) acc[mt][nt][j] = 0.f;

    const int wm = (wid & 3) * 32;   // warp m offset
    const int wn = (wid >> 2) * 64;  // warp n offset
    const int i8 = lane & 7;
    const uint32_t a_off = (uint32_t)(i8 + ((lane >> 3) & 1) * 8) * PITCH + (lane >> 4) * 16;
    const uint32_t b_off = (uint32_t)(i8 + ((lane >> 4) & 1) * 8) * PITCH + ((lane >> 3) & 1) * 16;

    auto COMPUTE = [&](int st) {
        const uint32_t base = sb + (uint32_t)st * STAGE_B;
        const uint32_t aAh = base + (uint32_t)wm * PITCH + a_off;
        const uint32_t aBh = base + OFF_BH + (uint32_t)wn * PITCH + b_off;
        const uint32_t aBl = base + OFF_BL + (uint32_t)wn * PITCH + b_off;
#pragma unroll
        for (int ks = 0; ks < 2; ks++) {
            uint32_t ah[2][4], al[2][4], bh[4][4], bl[4][4];
#pragma unroll
            for (int mt = 0; mt < 2; mt++) {
                ldsm4(ah[mt], aAh + mt * 16 * PITCH + ks * 32);
                if (NPROD == 3) ldsm4(al[mt], aAh + OFF_AL + mt * 16 * PITCH + ks * 32);
            }
#pragma unroll
            for (int nt = 0; nt < 4; nt++) {
                ldsm4(bh[nt], aBh + nt * 16 * PITCH + ks * 32);
                ldsm4(bl[nt], aBl + nt * 16 * PITCH + ks * 32);
            }
#pragma unroll
            for (int mt = 0; mt < 2; mt++)
#pragma unroll
                for (int nt = 0; nt < 8; nt++)
                    mma_bf16(acc[mt][nt], ah[mt], &bh[nt >> 1][(nt & 1) * 2]);
#pragma unroll
            for (int mt = 0; mt < 2; mt++)
#pragma unroll
                for (int nt = 0; nt < 8; nt++)
                    mma_bf16(acc[mt][nt], ah[mt], &bl[nt >> 1][(nt & 1) * 2]);
            if (NPROD == 3) {
#pragma unroll
                for (int mt = 0; mt < 2; mt++)
#pragma unroll
                    for (int nt = 0; nt < 8; nt++)
                        mma_bf16(acc[mt][nt], al[mt], &bh[nt >> 1][(nt & 1) * 2]);
            }
        }
    };

    FETCH(0, 0);
    FETCH(1, 1);

    for (int kt = 0; kt < nkt; kt++) {
        const int st = kt % STAGES;
        if (kt + 1 < nkt) { CP_WAIT1(); } else { CP_WAIT0(); }
        __syncthreads();
        COMPUTE(st);
        if (kt + 2 < nkt) FETCH(kt + 2, (kt + 2) % STAGES);
    }

    // Epilogue
    float* Cb = WF32 ? (C + (long long)bz * sC) : nullptr;
    __nv_bfloat16* Hh = WHI ? (Chi + (long long)bz * sC) : nullptr;
    __nv_bfloat16* Hl = WLO ? (Clo + (long long)bz * sC) : nullptr;
    const float* Rb = RESID ? (resid + (long long)bz * sC) : nullptr;

    const int r0 = lane >> 2;
    const int c0 = (lane & 3) * 2;
#pragma unroll
    for (int mt = 0; mt < 2; mt++) {
#pragma unroll
        for (int nt = 0; nt < 8; nt++) {
            const int col = n0 + wn + nt * 8 + c0;
#pragma unroll
            for (int h = 0; h < 2; h++) {
                const long long row = m0 + wm + mt * 16 + r0 + h * 8;
                float v0 = acc[mt][nt][h * 2 + 0] * alpha;
                float v1 = acc[mt][nt][h * 2 + 1] * alpha;
                if (BIAS)  { v0 += bias[col]; v1 += bias[col + 1]; }
                if (RESID) {
                    v0 += Rb[row * N + col];
                    v1 += Rb[row * N + col + 1];
                }
                if (WF32) {
                    float2 o = {v0, v1};
                    *reinterpret_cast<float2*>(&Cb[row * N + col]) = o;
                }
                if (WHI) {
                    __nv_bfloat16 h0 = __float2bfloat16(v0);
                    __nv_bfloat16 h1 = __float2bfloat16(v1);
                    __nv_bfloat162 hp; hp.x = h0; hp.y = h1;
                    *reinterpret_cast<__nv_bfloat162*>(&Hh[row * N + col]) = hp;
                    if (WLO) {
                        __nv_bfloat162 lp;
                        lp.x = __float2bfloat16(v0 - __bfloat162float(h0));
                        lp.y = __float2bfloat16(v1 - __bfloat162float(h1));
                        *reinterpret_cast<__nv_bfloat162*>(&Hl[row * N + col]) = lp;
                    }
                }
            }
        }
    }
}

// ---------------------------------------------------------------------------
// fp32 -> bf16 hi/lo split (vectorized by 4)
// ---------------------------------------------------------------------------
__global__ void __launch_bounds__(256)
split_kernel(const float* __restrict__ x, __nv_bfloat16* __restrict__ hi,
             __nv_bfloat16* __restrict__ lo, int n4) {
    const int i = blockIdx.x * 256 + threadIdx.x;
    if (i >= n4) return;
    const float4 v = reinterpret_cast<const float4*>(x)[i];
    __nv_bfloat16 h0 = __float2bfloat16(v.x), h1 = __float2bfloat16(v.y);
    __nv_bfloat16 h2 = __float2bfloat16(v.z), h3 = __float2bfloat16(v.w);
    __nv_bfloat162 hp0; hp0.x = h0; hp0.y = h1;
    __nv_bfloat162 hp1; hp1.x = h2; hp1.y = h3;
    __nv_bfloat162 lp0, lp1;
    lp0.x = __float2bfloat16(v.x - __bfloat162float(h0));
    lp0.y = __float2bfloat16(v.y - __bfloat162float(h1));
    lp1.x = __float2bfloat16(v.z - __bfloat162float(h2));
    lp1.y = __float2bfloat16(v.w - __bfloat162float(h3));
    reinterpret_cast<__nv_bfloat162*>(hi)[2 * i]     = hp0;
    reinterpret_cast<__nv_bfloat162*>(hi)[2 * i + 1] = hp1;
    reinterpret_cast<__nv_bfloat162*>(lo)[2 * i]     = lp0;
    reinterpret_cast<__nv_bfloat162*>(lo)[2 * i + 1] = lp1;
}

// ---------------------------------------------------------------------------
// Mask dtype probe (bool vs 4-byte): byte offset %4==1 nonzero => 1-byte bool
// ---------------------------------------------------------------------------
__global__ void detect_mask_kernel(const unsigned char* __restrict__ mask) {
    __shared__ int found;
    if (threadIdx.x == 0) found = 0;
    __syncthreads();
    for (int i = threadIdx.x; i < 1024; i += 256)
        if (mask[i * 4 + 1] != 0) found = 1;
    __syncthreads();
    if (threadIdx.x == 0) g_mask4 = found ? 0 : 1;
}

// ---------------------------------------------------------------------------
// Mask + softmax: fp32 scores -> bf16 probabilities (hi only)
// ---------------------------------------------------------------------------
__global__ void __launch_bounds__(256)
softmax_mask_kernel(const float* __restrict__ scores, const void* __restrict__ mask,
                    __nv_bfloat16* __restrict__ phi) {
    const long long row = blockIdx.x;
    const float* sr = scores + row * SS;
    const long long mbase = row * SS;
    const int tid = threadIdx.x;
    const int is4 = g_mask4;

    float vals[8];
    float mx = -3.0e38f;
#pragma unroll
    for (int i = 0; i < 8; i++) {
        const int c = tid + (i << 8);
        float x = sr[c];
        bool m;
        if (is4) m = reinterpret_cast<const unsigned int*>(mask)[mbase + c] != 0u;
        else     m = reinterpret_cast<const unsigned char*>(mask)[mbase + c] != 0;
        x = m ? -1e9f : x;
        vals[i] = x;
        mx = fmaxf(mx, x);
    }
    __shared__ float sred[8];
#pragma unroll
    for (int o = 16; o > 0; o >>= 1) mx = fmaxf(mx, __shfl_xor_sync(0xffffffffu, mx, o));
    if ((tid & 31) == 0) sred[tid >> 5] = mx;
    __syncthreads();
    float bm = sred[0];
#pragma unroll
    for (int w = 1; w < 8; w++) bm = fmaxf(bm, sred[w]);

    float sum = 0.f;
#pragma unroll
    for (int i = 0; i < 8; i++) {
        const float e = __expf(vals[i] - bm);
        vals[i] = e;
        sum += e;
    }
#pragma unroll
    for (int o = 16; o > 0; o >>= 1) sum += __shfl_xor_sync(0xffffffffu, sum, o);
    __shared__ float ssum[8];
    if ((tid & 31) == 0) ssum[tid >> 5] = sum;
    __syncthreads();
    float ts = 0.f;
#pragma unroll
    for (int w = 0; w < 8; w++) ts += ssum[w];

    const float inv = 1.0f / ts;
#pragma unroll
    for (int i = 0; i < 8; i += 2) {
        const int c = tid + (i << 8);
        __nv_bfloat162 hp;
        hp.x = __float2bfloat16(vals[i] * inv);
        hp.y = __float2bfloat16(vals[i + 1] * inv);
        // columns i and i+1 are 256 apart; store separately
        phi[mbase + c]       = hp.x;
        phi[mbase + c + 256] = hp.y;
    }
}

// ---------------------------------------------------------------------------
// kernel_launch
// ---------------------------------------------------------------------------
extern "C" void kernel_launch(void* const* d_in, const int* in_sizes, int n_in,
                              void* d_out, int out_size) {
    const float* Q    = (const float*)d_in[0];
    const float* Kin  = (const float*)d_in[1];
    const void*  mask = (const void*)d_in[2];
    const float* Wq   = (const float*)d_in[3];
    const float* Wk   = (const float*)d_in[4];
    const float* Wv   = (const float*)d_in[5];
    const float* Wp   = (const float*)d_in[6];
    const float* bp   = (const float*)d_in[7];
    float* out        = (float*)d_out;

    __nv_bfloat16 *Qhi, *Qlo, *Khi, *Klo, *Wqhi, *Wqlo, *Wkhi, *Wklo, *Wvhi, *Wvlo, *Wphi2, *Wplo2;
    __nv_bfloat16 *qhi, *khi, *klo, *vThi, *vTlo, *phi, *aohi;
    float *qf, *sc;
    cudaGetSymbolAddress((void**)&Qhi, g_Qhi);   cudaGetSymbolAddress((void**)&Qlo, g_Qlo);
    cudaGetSymbolAddress((void**)&Khi, g_Khi);   cudaGetSymbolAddress((void**)&Klo, g_Klo);
    cudaGetSymbolAddress((void**)&Wqhi, g_Wqhi); cudaGetSymbolAddress((void**)&Wqlo, g_Wqlo);
    cudaGetSymbolAddress((void**)&Wkhi, g_Wkhi); cudaGetSymbolAddress((void**)&Wklo, g_Wklo);
    cudaGetSymbolAddress((void**)&Wvhi, g_Wvhi); cudaGetSymbolAddress((void**)&Wvlo, g_Wvlo);
    cudaGetSymbolAddress((void**)&Wphi2, g_Wphi); cudaGetSymbolAddress((void**)&Wplo2, g_Wplo);
    cudaGetSymbolAddress((void**)&qf, g_qf);
    cudaGetSymbolAddress((void**)&qhi, g_qhi);
    cudaGetSymbolAddress((void**)&khi, g_khi);   cudaGetSymbolAddress((void**)&klo, g_klo);
    cudaGetSymbolAddress((void**)&vThi, g_vThi); cudaGetSymbolAddress((void**)&vTlo, g_vTlo);
    cudaGetSymbolAddress((void**)&sc, g_scores);
    cudaGetSymbolAddress((void**)&phi, g_phi);
    cudaGetSymbolAddress((void**)&aohi, g_aohi);

    constexpr int SMEM2 = STAGES * 3 * TILE_B;   // 2-product: 92160
    constexpr int SMEM3 = STAGES * 4 * TILE_B;   // 3-product: 122880
    cudaFuncSetAttribute(hmma_gemm<3, false, false, true,  true,  false>,
                         cudaFuncAttributeMaxDynamicSharedMemorySize, SMEM3);
    cudaFuncSetAttribute(hmma_gemm<2, false, false, false, true,  true >,
                         cudaFuncAttributeMaxDynamicSharedMemorySize, SMEM2);
    cudaFuncSetAttribute(hmma_gemm<2, false, false, true,  false, false>,
                         cudaFuncAttributeMaxDynamicSharedMemorySize, SMEM2);
    cudaFuncSetAttribute(hmma_gemm<2, false, false, false, true,  false>,
                         cudaFuncAttributeMaxDynamicSharedMemorySize, SMEM2);
    cudaFuncSetAttribute(hmma_gemm<2, true,  true,  true,  false, false>,
                         cudaFuncAttributeMaxDynamicSharedMemorySize, SMEM2);

    const float scale = 0.04419417382415922f;  // 512^-0.5
    const long long sQKV = (long long)SS * EE;
    const long long sSC  = (long long)SS * SS;
    dim3 blk(256);

    // 1) splits
    {
        const int nQ4 = MTOT * EE / 4, nW4 = EE * EE / 4;
        split_kernel<<<(nQ4 + 255) / 256, blk>>>(Q,   Qhi, Qlo, nQ4);
        split_kernel<<<(nQ4 + 255) / 256, blk>>>(Kin, Khi, Klo, nQ4);
        split_kernel<<<(nW4 + 255) / 256, blk>>>(Wq, Wqhi, Wqlo, nW4);
        split_kernel<<<(nW4 + 255) / 256, blk>>>(Wk, Wkhi, Wklo, nW4);
        split_kernel<<<(nW4 + 255) / 256, blk>>>(Wv, Wvhi, Wvlo, nW4);
        split_kernel<<<(nW4 + 255) / 256, blk>>>(Wp, Wphi2, Wplo2, nW4);
    }
    detect_mask_kernel<<<1, 256>>>((const unsigned char*)mask);

    // 2) q = Q Wq^T  (3-product; residual-critical) -> qf fp32 + qhi
    hmma_gemm<3, false, false, true, true, false><<<dim3(EE / 128, MTOT / 128, 1), blk, SMEM3>>>(
        Qhi, Qlo, Wqhi, Wqlo, qf, qhi, nullptr, MTOT, EE, EE, 0, 0, 0, 1.f, nullptr, nullptr);
    // 3) k = K Wk^T  (2-product: Kh*Wkh + Kh*Wkl) -> khi, klo
    hmma_gemm<2, false, false, false, true, true><<<dim3(EE / 128, MTOT / 128, 1), blk, SMEM2>>>(
        Khi, nullptr, Wkhi, Wklo, nullptr, khi, klo, MTOT, EE, EE, 0, 0, 0, 1.f, nullptr, nullptr);
    // 4) vT[b] = Wv K[b]^T  (2-product: Wvh*Kh + Wvh*Kl) -> vThi, vTlo
    hmma_gemm<2, false, false, false, true, true><<<dim3(SS / 128, EE / 128, BB), blk, SMEM2>>>(
        Wvhi, nullptr, Khi, Klo, nullptr, vThi, vTlo, EE, SS, EE,
        0, sQKV, (long long)EE * SS, 1.f, nullptr, nullptr);
    // 5) scores[b] = scale * q[b] k[b]^T  (2-product: qh*kh + qh*kl) -> fp32
    hmma_gemm<2, false, false, true, false, false><<<dim3(SS / 128, SS / 128, BB), blk, SMEM2>>>(
        qhi, nullptr, khi, klo, sc, nullptr, nullptr, SS, SS, EE,
        sQKV, sQKV, sSC, scale, nullptr, nullptr);
    // 6) mask + softmax -> phi (bf16)
    softmax_mask_kernel<<<BB * SS, blk>>>(sc, mask, phi);
    // 7) ao[b] = p[b] vT[b]^T  (2-product: p*vh + p*vl) -> aohi
    hmma_gemm<2, false, false, false, true, false><<<dim3(EE / 128, SS / 128, BB), blk, SMEM2>>>(
        phi, nullptr, vThi, vTlo, nullptr, aohi, nullptr, SS, EE, SS,
        sSC, (long long)EE * SS, sQKV, 1.f, nullptr, nullptr);
    // 8) out = ao Wp^T + bp + q  (2-product: aoh*Wph + aoh*Wpl)
    hmma_gemm<2, true, true, true, false, false><<<dim3(EE / 128, MTOT / 128, 1), blk, SMEM2>>>(
        aohi, nullptr, Wphi2, Wplo2, out, nullptr, nullptr, MTOT, EE, EE,
        0, 0, 0, 1.f, bp, qf);
}

// round 5
// speedup vs baseline: 5.8837x; 1.3638x over previous
#include <cuda_runtime.h>
#include <cuda_bf16.h>
#include <cstdint>

#define BB 8
#define SS 2048
#define EE 512
#define MTOT (BB * SS)

// ---------------------------------------------------------------------------
// Scratch (__device__ globals; no allocation anywhere)
// ---------------------------------------------------------------------------
__device__ __nv_bfloat16 g_Qhi[(size_t)MTOT * EE], g_Qlo[(size_t)MTOT * EE];
__device__ __nv_bfloat16 g_Khi[(size_t)MTOT * EE], g_Klo[(size_t)MTOT * EE];
__device__ __nv_bfloat16 g_Wqhi[EE * EE], g_Wqlo[EE * EE];
__device__ __nv_bfloat16 g_Wkhi[EE * EE], g_Wklo[EE * EE];
__device__ __nv_bfloat16 g_Wvhi[EE * EE], g_Wvlo[EE * EE];
__device__ __nv_bfloat16 g_Wphi[EE * EE], g_Wplo[EE * EE];
__device__ float         g_qf [(size_t)MTOT * EE];
__device__ __nv_bfloat16 g_qhi[(size_t)MTOT * EE];
__device__ __nv_bfloat16 g_khi[(size_t)MTOT * EE];
__device__ __nv_bfloat16 g_vThi[(size_t)BB * EE * SS];
__device__ float         g_scores[(size_t)BB * SS * SS];
__device__ __nv_bfloat16 g_phi[(size_t)BB * SS * SS];
__device__ __nv_bfloat16 g_aohi[(size_t)MTOT * EE];
__device__ int           g_mask4;

// ---------------------------------------------------------------------------
// Helpers (baseline PTX only; legal at .target sm_103)
// ---------------------------------------------------------------------------
__device__ __forceinline__ uint32_t smem_u32(const void* p) {
    uint32_t a;
    asm("{ .reg .u64 t; cvta.to.shared.u64 t, %1; cvt.u32.u64 %0, t; }"
        : "=r"(a) : "l"(p));
    return a;
}
__device__ __forceinline__ void cpasync16(uint32_t dst, const void* src) {
    asm volatile("cp.async.cg.shared.global [%0], [%1], 16;"
                 :: "r"(dst), "l"(src) : "memory");
}
#define CP_COMMIT() asm volatile("cp.async.commit_group;" ::: "memory")
#define CP_WAIT1()  asm volatile("cp.async.wait_group 1;" ::: "memory")
#define CP_WAIT0()  asm volatile("cp.async.wait_group 0;" ::: "memory")

__device__ __forceinline__ void ldsm4(uint32_t* r, uint32_t addr) {
    asm volatile("ldmatrix.sync.aligned.m8n8.x4.shared.b16 {%0,%1,%2,%3}, [%4];"
                 : "=r"(r[0]), "=r"(r[1]), "=r"(r[2]), "=r"(r[3]) : "r"(addr));
}
__device__ __forceinline__ void mma_bf16(float* d, const uint32_t* a, const uint32_t* b) {
    asm volatile(
        "mma.sync.aligned.m16n8k16.row.col.f32.bf16.bf16.f32 "
        "{%0,%1,%2,%3}, {%4,%5,%6,%7}, {%8,%9}, {%0,%1,%2,%3};"
        : "+f"(d[0]), "+f"(d[1]), "+f"(d[2]), "+f"(d[3])
        : "r"(a[0]), "r"(a[1]), "r"(a[2]), "r"(a[3]), "r"(b[0]), "r"(b[1]));
}

// SMEM tile: 128 rows x 64 bf16 (128 B data), pitch 144 B => conflict-free
#define PITCH    144
#define TILE_B   (128 * PITCH)          // 18432
#define STAGES   3

// ---------------------------------------------------------------------------
// HMMA NT GEMM: C[M,N] = alpha * A[M,K] * B[N,K]^T, bf16, fp32 acc.
// NPROD=1: Ah*Bh.  NPROD=2: Ah*Bh + Ah*Bl.  NPROD=3: + Al*Bh.
// BM=BN=128, BK=64, 256 threads, warp tile 32x64, 3-stage cp.async pipeline,
// one __syncthreads per K-iter. Requires M%128==0, N%128==0, K%64==0, nkt>=2.
// ---------------------------------------------------------------------------
template <int NPROD, bool BIAS, bool RESID, bool WF32, bool WHI, bool WLO>
__global__ void __launch_bounds__(256, 1)
hmma_gemm(const __nv_bfloat16* __restrict__ Ahi, const __nv_bfloat16* __restrict__ Alo,
          const __nv_bfloat16* __restrict__ Bhi, const __nv_bfloat16* __restrict__ Blo,
          float* __restrict__ C, __nv_bfloat16* __restrict__ Chi,
          __nv_bfloat16* __restrict__ Clo,
          int M, int N, int K,
          long long sA, long long sB, long long sC,
          float alpha, const float* __restrict__ bias, const float* __restrict__ resid) {
    constexpr int NT      = (NPROD == 1) ? 2 : (NPROD == 2) ? 3 : 4;
    constexpr int STAGE_B = NT * TILE_B;
    constexpr uint32_t OFF_AL = TILE_B;                              // NPROD==3
    constexpr uint32_t OFF_BH = (NPROD == 3) ? 2u * TILE_B : TILE_B;
    constexpr uint32_t OFF_BL = OFF_BH + TILE_B;                     // NPROD>=2

    extern __shared__ __align__(128) char smem[];
    const uint32_t sb = smem_u32(smem);

    const int tid  = threadIdx.x;
    const int wid  = tid >> 5;
    const int lane = tid & 31;
    const int bz   = blockIdx.z;
    const int m0   = blockIdx.y * 128;
    const int n0   = blockIdx.x * 128;

    const __nv_bfloat16* Ah = Ahi + (long long)bz * sA;
    const __nv_bfloat16* Al = (NPROD == 3) ? (Alo + (long long)bz * sA) : nullptr;
    const __nv_bfloat16* Bh = Bhi + (long long)bz * sB;
    const __nv_bfloat16* Bl = (NPROD >= 2) ? (Blo + (long long)bz * sB) : nullptr;

    const int nkt = K >> 6;

    auto FETCH = [&](int kt, int st) {
        const uint32_t base = sb + (uint32_t)st * STAGE_B;
#pragma unroll
        for (int t = 0; t < 4; t++) {
            const int c   = tid + t * 256;       // 0..1023
            const int row = c >> 3;              // 0..127
            const int cp  = c & 7;               // 16B chunk within 128B row
            const uint32_t doff = row * PITCH + cp * 16;
            const long long ga = (long long)(m0 + row) * K + (kt << 6) + cp * 8;
            const long long gb = (long long)(n0 + row) * K + (kt << 6) + cp * 8;
            cpasync16(base + doff, Ah + ga);
            if (NPROD == 3) cpasync16(base + OFF_AL + doff, Al + ga);
            cpasync16(base + OFF_BH + doff, Bh + gb);
            if (NPROD >= 2) cpasync16(base + OFF_BL + doff, Bl + gb);
        }
        CP_COMMIT();
    };

    float acc[2][8][4];
#pragma unroll
    for (int mt = 0; mt < 2; mt++)
#pragma unroll
        for (int nt = 0; nt < 8; nt++)
#pragma unroll
            for (int j = 0; j < 4; j++) acc[mt][nt][j] = 0.f;

    const int wm = (wid & 3) * 32;   // warp m offset
    const int wn = (wid >> 2) * 64;  // warp n offset
    const int i8 = lane & 7;
    const uint32_t a_off = (uint32_t)(i8 + ((lane >> 3) & 1) * 8) * PITCH + (lane >> 4) * 16;
    const uint32_t b_off = (uint32_t)(i8 + ((lane >> 4) & 1) * 8) * PITCH + ((lane >> 3) & 1) * 16;

    auto COMPUTE = [&](int st) {
        const uint32_t base = sb + (uint32_t)st * STAGE_B;
        const uint32_t aAh = base + (uint32_t)wm * PITCH + a_off;
        const uint32_t aBh = base + OFF_BH + (uint32_t)wn * PITCH + b_off;
        const uint32_t aBl = base + OFF_BL + (uint32_t)wn * PITCH + b_off;
#pragma unroll
        for (int ks = 0; ks < 4; ks++) {
            uint32_t ah[2][4], al[2][4], bh[4][4], bl[4][4];
#pragma unroll
            for (int mt = 0; mt < 2; mt++) {
                ldsm4(ah[mt], aAh + mt * 16 * PITCH + ks * 32);
                if (NPROD == 3) ldsm4(al[mt], aAh + OFF_AL + mt * 16 * PITCH + ks * 32);
            }
#pragma unroll
            for (int nt = 0; nt < 4; nt++) {
                ldsm4(bh[nt], aBh + nt * 16 * PITCH + ks * 32);
                if (NPROD >= 2) ldsm4(bl[nt], aBl + nt * 16 * PITCH + ks * 32);
            }
#pragma unroll
            for (int mt = 0; mt < 2; mt++)
#pragma unroll
                for (int nt = 0; nt < 8; nt++)
                    mma_bf16(acc[mt][nt], ah[mt], &bh[nt >> 1][(nt & 1) * 2]);
            if (NPROD >= 2) {
#pragma unroll
                for (int mt = 0; mt < 2; mt++)
#pragma unroll
                    for (int nt = 0; nt < 8; nt++)
                        mma_bf16(acc[mt][nt], ah[mt], &bl[nt >> 1][(nt & 1) * 2]);
            }
            if (NPROD == 3) {
#pragma unroll
                for (int mt = 0; mt < 2; mt++)
#pragma unroll
                    for (int nt = 0; nt < 8; nt++)
                        mma_bf16(acc[mt][nt], al[mt], &bh[nt >> 1][(nt & 1) * 2]);
            }
        }
    };

    FETCH(0, 0);
    FETCH(1, 1);

    for (int kt = 0; kt < nkt; kt++) {
        const int st = kt % STAGES;
        if (kt + 1 < nkt) { CP_WAIT1(); } else { CP_WAIT0(); }
        __syncthreads();
        COMPUTE(st);
        if (kt + 2 < nkt) FETCH(kt + 2, (kt + 2) % STAGES);
    }

    // Epilogue
    float* Cb = WF32 ? (C + (long long)bz * sC) : nullptr;
    __nv_bfloat16* Hh = WHI ? (Chi + (long long)bz * sC) : nullptr;
    __nv_bfloat16* Hl = WLO ? (Clo + (long long)bz * sC) : nullptr;
    const float* Rb = RESID ? (resid + (long long)bz * sC) : nullptr;

    const int r0 = lane >> 2;
    const int c0 = (lane & 3) * 2;
#pragma unroll
    for (int mt = 0; mt < 2; mt++) {
#pragma unroll
        for (int nt = 0; nt < 8; nt++) {
            const int col = n0 + wn + nt * 8 + c0;
#pragma unroll
            for (int h = 0; h < 2; h++) {
                const long long row = m0 + wm + mt * 16 + r0 + h * 8;
                float v0 = acc[mt][nt][h * 2 + 0] * alpha;
                float v1 = acc[mt][nt][h * 2 + 1] * alpha;
                if (BIAS)  { v0 += bias[col]; v1 += bias[col + 1]; }
                if (RESID) {
                    v0 += Rb[row * N + col];
                    v1 += Rb[row * N + col + 1];
                }
                if (WF32) {
                    float2 o = {v0, v1};
                    *reinterpret_cast<float2*>(&Cb[row * N + col]) = o;
                }
                if (WHI) {
                    __nv_bfloat16 h0 = __float2bfloat16(v0);
                    __nv_bfloat16 h1 = __float2bfloat16(v1);
                    __nv_bfloat162 hp; hp.x = h0; hp.y = h1;
                    *reinterpret_cast<__nv_bfloat162*>(&Hh[row * N + col]) = hp;
                    if (WLO) {
                        __nv_bfloat162 lp;
                        lp.x = __float2bfloat16(v0 - __bfloat162float(h0));
                        lp.y = __float2bfloat16(v1 - __bfloat162float(h1));
                        *reinterpret_cast<__nv_bfloat162*>(&Hl[row * N + col]) = lp;
                    }
                }
            }
        }
    }
}

// ---------------------------------------------------------------------------
// fp32 -> bf16 hi/lo split (vectorized by 4)
// ---------------------------------------------------------------------------
__global__ void __launch_bounds__(256)
split_kernel(const float* __restrict__ x, __nv_bfloat16* __restrict__ hi,
             __nv_bfloat16* __restrict__ lo, int n4) {
    const int i = blockIdx.x * 256 + threadIdx.x;
    if (i >= n4) return;
    const float4 v = reinterpret_cast<const float4*>(x)[i];
    __nv_bfloat16 h0 = __float2bfloat16(v.x), h1 = __float2bfloat16(v.y);
    __nv_bfloat16 h2 = __float2bfloat16(v.z), h3 = __float2bfloat16(v.w);
    __nv_bfloat162 hp0; hp0.x = h0; hp0.y = h1;
    __nv_bfloat162 hp1; hp1.x = h2; hp1.y = h3;
    __nv_bfloat162 lp0, lp1;
    lp0.x = __float2bfloat16(v.x - __bfloat162float(h0));
    lp0.y = __float2bfloat16(v.y - __bfloat162float(h1));
    lp1.x = __float2bfloat16(v.z - __bfloat162float(h2));
    lp1.y = __float2bfloat16(v.w - __bfloat162float(h3));
    reinterpret_cast<__nv_bfloat162*>(hi)[2 * i]     = hp0;
    reinterpret_cast<__nv_bfloat162*>(hi)[2 * i + 1] = hp1;
    reinterpret_cast<__nv_bfloat162*>(lo)[2 * i]     = lp0;
    reinterpret_cast<__nv_bfloat162*>(lo)[2 * i + 1] = lp1;
}

// ---------------------------------------------------------------------------
// Mask dtype probe (bool vs 4-byte): byte offset %4==1 nonzero => 1-byte bool
// ---------------------------------------------------------------------------
__global__ void detect_mask_kernel(const unsigned char* __restrict__ mask) {
    __shared__ int found;
    if (threadIdx.x == 0) found = 0;
    __syncthreads();
    for (int i = threadIdx.x; i < 1024; i += 256)
        if (mask[i * 4 + 1] != 0) found = 1;
    __syncthreads();
    if (threadIdx.x == 0) g_mask4 = found ? 0 : 1;
}

// ---------------------------------------------------------------------------
// Mask + softmax: fp32 scores -> bf16 probabilities (hi only)
// ---------------------------------------------------------------------------
__global__ void __launch_bounds__(256)
softmax_mask_kernel(const float* __restrict__ scores, const void* __restrict__ mask,
                    __nv_bfloat16* __restrict__ phi) {
    const long long row = blockIdx.x;
    const float* sr = scores + row * SS;
    const long long mbase = row * SS;
    const int tid = threadIdx.x;
    const int is4 = g_mask4;

    float vals[8];
    float mx = -3.0e38f;
#pragma unroll
    for (int i = 0; i < 8; i++) {
        const int c = tid + (i << 8);
        float x = sr[c];
        bool m;
        if (is4) m = reinterpret_cast<const unsigned int*>(mask)[mbase + c] != 0u;
        else     m = reinterpret_cast<const unsigned char*>(mask)[mbase + c] != 0;
        x = m ? -1e9f : x;
        vals[i] = x;
        mx = fmaxf(mx, x);
    }
    __shared__ float sred[8];
#pragma unroll
    for (int o = 16; o > 0; o >>= 1) mx = fmaxf(mx, __shfl_xor_sync(0xffffffffu, mx, o));
    if ((tid & 31) == 0) sred[tid >> 5] = mx;
    __syncthreads();
    float bm = sred[0];
#pragma unroll
    for (int w = 1; w < 8; w++) bm = fmaxf(bm, sred[w]);

    float sum = 0.f;
#pragma unroll
    for (int i = 0; i < 8; i++) {
        const float e = __expf(vals[i] - bm);
        vals[i] = e;
        sum += e;
    }
#pragma unroll
    for (int o = 16; o > 0; o >>= 1) sum += __shfl_xor_sync(0xffffffffu, sum, o);
    __shared__ float ssum[8];
    if ((tid & 31) == 0) ssum[tid >> 5] = sum;
    __syncthreads();
    float ts = 0.f;
#pragma unroll
    for (int w = 0; w < 8; w++) ts += ssum[w];

    const float inv = 1.0f / ts;
#pragma unroll
    for (int i = 0; i < 8; i++) {
        const int c = tid + (i << 8);
        phi[mbase + c] = __float2bfloat16(vals[i] * inv);
    }
}

// ---------------------------------------------------------------------------
// kernel_launch
// ---------------------------------------------------------------------------
extern "C" void kernel_launch(void* const* d_in, const int* in_sizes, int n_in,
                              void* d_out, int out_size) {
    const float* Q    = (const float*)d_in[0];
    const float* Kin  = (const float*)d_in[1];
    const void*  mask = (const void*)d_in[2];
    const float* Wq   = (const float*)d_in[3];
    const float* Wk   = (const float*)d_in[4];
    const float* Wv   = (const float*)d_in[5];
    const float* Wp   = (const float*)d_in[6];
    const float* bp   = (const float*)d_in[7];
    float* out        = (float*)d_out;

    __nv_bfloat16 *Qhi, *Qlo, *Khi, *Klo, *Wqhi, *Wqlo, *Wkhi, *Wklo, *Wvhi, *Wvlo, *Wphi2, *Wplo2;
    __nv_bfloat16 *qhi, *khi, *vThi, *phi, *aohi;
    float *qf, *sc;
    cudaGetSymbolAddress((void**)&Qhi, g_Qhi);   cudaGetSymbolAddress((void**)&Qlo, g_Qlo);
    cudaGetSymbolAddress((void**)&Khi, g_Khi);   cudaGetSymbolAddress((void**)&Klo, g_Klo);
    cudaGetSymbolAddress((void**)&Wqhi, g_Wqhi); cudaGetSymbolAddress((void**)&Wqlo, g_Wqlo);
    cudaGetSymbolAddress((void**)&Wkhi, g_Wkhi); cudaGetSymbolAddress((void**)&Wklo, g_Wklo);
    cudaGetSymbolAddress((void**)&Wvhi, g_Wvhi); cudaGetSymbolAddress((void**)&Wvlo, g_Wvlo);
    cudaGetSymbolAddress((void**)&Wphi2, g_Wphi); cudaGetSymbolAddress((void**)&Wplo2, g_Wplo);
    cudaGetSymbolAddress((void**)&qf, g_qf);
    cudaGetSymbolAddress((void**)&qhi, g_qhi);
    cudaGetSymbolAddress((void**)&khi, g_khi);
    cudaGetSymbolAddress((void**)&vThi, g_vThi);
    cudaGetSymbolAddress((void**)&sc, g_scores);
    cudaGetSymbolAddress((void**)&phi, g_phi);
    cudaGetSymbolAddress((void**)&aohi, g_aohi);

    constexpr int SMEM1 = STAGES * 2 * TILE_B;   // 110592
    constexpr int SMEM2 = STAGES * 3 * TILE_B;   // 165888
    constexpr int SMEM3 = STAGES * 4 * TILE_B;   // 221184
    cudaFuncSetAttribute(hmma_gemm<3, false, false, true,  true,  false>,
                         cudaFuncAttributeMaxDynamicSharedMemorySize, SMEM3);
    cudaFuncSetAttribute(hmma_gemm<2, false, false, false, true,  false>,
                         cudaFuncAttributeMaxDynamicSharedMemorySize, SMEM2);
    cudaFuncSetAttribute(hmma_gemm<1, false, false, true,  false, false>,
                         cudaFuncAttributeMaxDynamicSharedMemorySize, SMEM1);
    cudaFuncSetAttribute(hmma_gemm<1, false, false, false, true,  false>,
                         cudaFuncAttributeMaxDynamicSharedMemorySize, SMEM1);
    cudaFuncSetAttribute(hmma_gemm<2, true,  true,  true,  false, false>,
                         cudaFuncAttributeMaxDynamicSharedMemorySize, SMEM2);

    const float scale = 0.04419417382415922f;  // 512^-0.5
    const long long sQKV = (long long)SS * EE;
    const long long sSC  = (long long)SS * SS;
    dim3 blk(256);

    // 1) splits
    {
        const int nQ4 = MTOT * EE / 4, nW4 = EE * EE / 4;
        split_kernel<<<(nQ4 + 255) / 256, blk>>>(Q,   Qhi, Qlo, nQ4);
        split_kernel<<<(nQ4 + 255) / 256, blk>>>(Kin, Khi, Klo, nQ4);
        split_kernel<<<(nW4 + 255) / 256, blk>>>(Wq, Wqhi, Wqlo, nW4);
        split_kernel<<<(nW4 + 255) / 256, blk>>>(Wk, Wkhi, Wklo, nW4);
        split_kernel<<<(nW4 + 255) / 256, blk>>>(Wv, Wvhi, Wvlo, nW4);
        split_kernel<<<(nW4 + 255) / 256, blk>>>(Wp, Wphi2, Wplo2, nW4);
    }
    detect_mask_kernel<<<1, 256>>>((const unsigned char*)mask);

    // 2) q = Q Wq^T  (3-product; residual-critical) -> qf fp32 + qhi
    hmma_gemm<3, false, false, true, true, false><<<dim3(EE / 128, MTOT / 128, 1), blk, SMEM3>>>(
        Qhi, Qlo, Wqhi, Wqlo, qf, qhi, nullptr, MTOT, EE, EE, 0, 0, 0, 1.f, nullptr, nullptr);
    // 3) k = K Wk^T  (2-product: Kh*Wkh + Kh*Wkl) -> khi
    hmma_gemm<2, false, false, false, true, false><<<dim3(EE / 128, MTOT / 128, 1), blk, SMEM2>>>(
        Khi, nullptr, Wkhi, Wklo, nullptr, khi, nullptr, MTOT, EE, EE, 0, 0, 0, 1.f, nullptr, nullptr);
    // 4) vT[b] = Wv K[b]^T  (2-product: Wvh*Kh + Wvh*Kl) -> vThi
    hmma_gemm<2, false, false, false, true, false><<<dim3(SS / 128, EE / 128, BB), blk, SMEM2>>>(
        Wvhi, nullptr, Khi, Klo, nullptr, vThi, nullptr, EE, SS, EE,
        0, sQKV, (long long)EE * SS, 1.f, nullptr, nullptr);
    // 5) scores[b] = scale * q[b] k[b]^T  (1-product) -> fp32
    hmma_gemm<1, false, false, true, false, false><<<dim3(SS / 128, SS / 128, BB), blk, SMEM1>>>(
        qhi, nullptr, khi, nullptr, sc, nullptr, nullptr, SS, SS, EE,
        sQKV, sQKV, sSC, scale, nullptr, nullptr);
    // 6) mask + softmax -> phi (bf16)
    softmax_mask_kernel<<<BB * SS, blk>>>(sc, mask, phi);
    // 7) ao[b] = p[b] vT[b]^T  (1-product) -> aohi
    hmma_gemm<1, false, false, false, true, false><<<dim3(EE / 128, SS / 128, BB), blk, SMEM1>>>(
        phi, nullptr, vThi, nullptr, nullptr, aohi, nullptr, SS, EE, SS,
        sSC, (long long)EE * SS, sQKV, 1.f, nullptr, nullptr);
    // 8) out = ao Wp^T + bp + q  (2-product: aoh*Wph + aoh*Wpl)
    hmma_gemm<2, true, true, true, false, false><<<dim3(EE / 128, MTOT / 128, 1), blk, SMEM2>>>(
        aohi, nullptr, Wphi2, Wplo2, out, nullptr, nullptr, MTOT, EE, EE,
        0, 0, 0, 1.f, bp, qf);
}

// round 6
// speedup vs baseline: 6.4743x; 1.1004x over previous
#include <cuda_runtime.h>
#include <cuda_bf16.h>
#include <cstdint>

#define BB 8
#define SS 2048
#define EE 512
#define MTOT (BB * SS)

// ---------------------------------------------------------------------------
// Scratch (__device__ globals; no allocation anywhere)
// ---------------------------------------------------------------------------
__device__ __nv_bfloat16 g_Qhi[(size_t)MTOT * EE], g_Qlo[(size_t)MTOT * EE];
__device__ __nv_bfloat16 g_Khi[(size_t)MTOT * EE], g_Klo[(size_t)MTOT * EE];
__device__ __nv_bfloat16 g_Wqhi[EE * EE], g_Wqlo[EE * EE];
__device__ __nv_bfloat16 g_Wkhi[EE * EE], g_Wklo[EE * EE];
__device__ __nv_bfloat16 g_Wvhi[EE * EE], g_Wvlo[EE * EE];
__device__ __nv_bfloat16 g_Wphi[EE * EE], g_Wplo[EE * EE];
__device__ float         g_qf [(size_t)MTOT * EE];
__device__ __nv_bfloat16 g_qhi[(size_t)MTOT * EE];
__device__ __nv_bfloat16 g_khi[(size_t)MTOT * EE];
__device__ __nv_bfloat16 g_vThi[(size_t)BB * EE * SS];
__device__ __nv_bfloat16 g_phi[(size_t)BB * SS * SS];   // scores (bf16) -> probs in place
__device__ __nv_bfloat16 g_aohi[(size_t)MTOT * EE];
__device__ int           g_mask4;

// ---------------------------------------------------------------------------
// Helpers (baseline PTX only; legal at .target sm_103)
// ---------------------------------------------------------------------------
__device__ __forceinline__ uint32_t smem_u32(const void* p) {
    uint32_t a;
    asm("{ .reg .u64 t; cvta.to.shared.u64 t, %1; cvt.u32.u64 %0, t; }"
        : "=r"(a) : "l"(p));
    return a;
}
__device__ __forceinline__ void cpasync16(uint32_t dst, const void* src) {
    asm volatile("cp.async.cg.shared.global [%0], [%1], 16;"
                 :: "r"(dst), "l"(src) : "memory");
}
#define CP_COMMIT() asm volatile("cp.async.commit_group;" ::: "memory")
#define CP_WAIT2()  asm volatile("cp.async.wait_group 2;" ::: "memory")
#define CP_WAIT1()  asm volatile("cp.async.wait_group 1;" ::: "memory")
#define CP_WAIT0()  asm volatile("cp.async.wait_group 0;" ::: "memory")

__device__ __forceinline__ void ldsm4(uint32_t* r, uint32_t addr) {
    asm volatile("ldmatrix.sync.aligned.m8n8.x4.shared.b16 {%0,%1,%2,%3}, [%4];"
                 : "=r"(r[0]), "=r"(r[1]), "=r"(r[2]), "=r"(r[3]) : "r"(addr));
}
__device__ __forceinline__ void mma_bf16(float* d, const uint32_t* a, const uint32_t* b) {
    asm volatile(
        "mma.sync.aligned.m16n8k16.row.col.f32.bf16.bf16.f32 "
        "{%0,%1,%2,%3}, {%4,%5,%6,%7}, {%8,%9}, {%0,%1,%2,%3};"
        : "+f"(d[0]), "+f"(d[1]), "+f"(d[2]), "+f"(d[3])
        : "r"(a[0]), "r"(a[1]), "r"(a[2]), "r"(a[3]), "r"(b[0]), "r"(b[1]));
}

// SMEM rows: 64 bf16 (128 B data), pitch 144 B => conflict-free ldmatrix
#define PITCH    144
#define BTILE_B  (128 * PITCH)          // 18432 (B tile is always 128 rows)

// ---------------------------------------------------------------------------
// HMMA NT GEMM: C[M,N] = alpha * A[M,K] * B[N,K]^T, bf16, fp32 acc.
// NPROD=1: Ah*Bh.  NPROD=2: Ah*Bh + Ah*Bl.  NPROD=3: + Al*Bh.
// Block BMx128, BK=64, 256 threads (8 warps: 4 m x 2 n, warp tile (BM/4)x64).
// STG-stage cp.async pipeline, one __syncthreads per K-iter.
// Requires M%BM==0, N%128==0, K%64==0, nkt>=STG.
// ---------------------------------------------------------------------------
template <int BM, int STG, int NPROD, bool BIAS, bool RESID, bool WF32, bool WHI, bool WLO>
__global__ void __launch_bounds__(256, 1)
hmma_gemm(const __nv_bfloat16* __restrict__ Ahi, const __nv_bfloat16* __restrict__ Alo,
          const __nv_bfloat16* __restrict__ Bhi, const __nv_bfloat16* __restrict__ Blo,
          float* __restrict__ C, __nv_bfloat16* __restrict__ Chi,
          __nv_bfloat16* __restrict__ Clo,
          int M, int N, int K,
          long long sA, long long sB, long long sC,
          float alpha, const float* __restrict__ bias, const float* __restrict__ resid) {
    constexpr int MT      = BM / 64;             // m16 tiles per warp
    constexpr uint32_t ATILE = (uint32_t)BM * PITCH;
    constexpr uint32_t OFF_AL = ATILE;                                // NPROD==3
    constexpr uint32_t OFF_BH = (NPROD == 3) ? 2u * ATILE : ATILE;
    constexpr uint32_t OFF_BL = OFF_BH + BTILE_B;                     // NPROD>=2
    constexpr uint32_t STAGE_B =
        ((NPROD == 3) ? 2u : 1u) * ATILE + ((NPROD >= 2) ? 2u : 1u) * BTILE_B;

    extern __shared__ __align__(128) char smem[];
    const uint32_t sb = smem_u32(smem);

    const int tid  = threadIdx.x;
    const int wid  = tid >> 5;
    const int lane = tid & 31;
    const int bz   = blockIdx.z;
    const int m0   = blockIdx.y * BM;
    const int n0   = blockIdx.x * 128;

    const __nv_bfloat16* Ah = Ahi + (long long)bz * sA;
    const __nv_bfloat16* Al = (NPROD == 3) ? (Alo + (long long)bz * sA) : nullptr;
    const __nv_bfloat16* Bh = Bhi + (long long)bz * sB;
    const __nv_bfloat16* Bl = (NPROD >= 2) ? (Blo + (long long)bz * sB) : nullptr;

    const int nkt = K >> 6;

    auto FETCH = [&](int kt, int st) {
        const uint32_t base = sb + (uint32_t)st * STAGE_B;
        // A tiles: BM rows x 8 chunks of 16 B
#pragma unroll
        for (int t = 0; t < BM / 32; t++) {
            const int c   = tid + t * 256;       // 0..BM*8-1
            const int row = c >> 3;
            const int cp  = c & 7;
            const uint32_t doff = row * PITCH + cp * 16;
            const long long ga = (long long)(m0 + row) * K + (kt << 6) + cp * 8;
            cpasync16(base + doff, Ah + ga);
            if (NPROD == 3) cpasync16(base + OFF_AL + doff, Al + ga);
        }
        // B tiles: 128 rows x 8 chunks
#pragma unroll
        for (int t = 0; t < 4; t++) {
            const int c   = tid + t * 256;
            const int row = c >> 3;
            const int cp  = c & 7;
            const uint32_t doff = row * PITCH + cp * 16;
            const long long gb = (long long)(n0 + row) * K + (kt << 6) + cp * 8;
            cpasync16(base + OFF_BH + doff, Bh + gb);
            if (NPROD >= 2) cpasync16(base + OFF_BL + doff, Bl + gb);
        }
        CP_COMMIT();
    };

    float acc[MT][8][4];
#pragma unroll
    for (int mt = 0; mt < MT; mt++)
#pragma unroll
        for (int nt = 0; nt < 8; nt++)
#pragma unroll
            for (int j = 0; j < 4; j++) acc[mt][nt][j] = 0.f;

    const int wm = (wid & 3) * (BM / 4);   // warp m offset
    const int wn = (wid >> 2) * 64;        // warp n offset
    const int i8 = lane & 7;
    const uint32_t a_off = (uint32_t)(i8 + ((lane >> 3) & 1) * 8) * PITCH + (lane >> 4) * 16;
    const uint32_t b_off = (uint32_t)(i8 + ((lane >> 4) & 1) * 8) * PITCH + ((lane >> 3) & 1) * 16;

    auto COMPUTE = [&](int st) {
        const uint32_t base = sb + (uint32_t)st * STAGE_B;
        const uint32_t aAh = base + (uint32_t)wm * PITCH + a_off;
        const uint32_t aBh = base + OFF_BH + (uint32_t)wn * PITCH + b_off;
        const uint32_t aBl = base + OFF_BL + (uint32_t)wn * PITCH + b_off;
#pragma unroll
        for (int ks = 0; ks < 4; ks++) {
            uint32_t ah[MT][4], al[MT][4], bh[4][4], bl[4][4];
#pragma unroll
            for (int mt = 0; mt < MT; mt++) {
                ldsm4(ah[mt], aAh + mt * 16 * PITCH + ks * 32);
                if (NPROD == 3) ldsm4(al[mt], aAh + OFF_AL + mt * 16 * PITCH + ks * 32);
            }
#pragma unroll
            for (int nt = 0; nt < 4; nt++) {
                ldsm4(bh[nt], aBh + nt * 16 * PITCH + ks * 32);
                if (NPROD >= 2) ldsm4(bl[nt], aBl + nt * 16 * PITCH + ks * 32);
            }
#pragma unroll
            for (int mt = 0; mt < MT; mt++)
#pragma unroll
                for (int nt = 0; nt < 8; nt++)
                    mma_bf16(acc[mt][nt], ah[mt], &bh[nt >> 1][(nt & 1) * 2]);
            if (NPROD >= 2) {
#pragma unroll
                for (int mt = 0; mt < MT; mt++)
#pragma unroll
                    for (int nt = 0; nt < 8; nt++)
                        mma_bf16(acc[mt][nt], ah[mt], &bl[nt >> 1][(nt & 1) * 2]);
            }
            if (NPROD == 3) {
#pragma unroll
                for (int mt = 0; mt < MT; mt++)
#pragma unroll
                    for (int nt = 0; nt < 8; nt++)
                        mma_bf16(acc[mt][nt], al[mt], &bh[nt >> 1][(nt & 1) * 2]);
            }
        }
    };

    // Prefetch STG-1 stages
    FETCH(0, 0);
    FETCH(1, 1);
    if (STG == 4) FETCH(2, 2);

    for (int kt = 0; kt < nkt; kt++) {
        const int st  = kt % STG;
        const int rem = nkt - kt - 1;
        if (STG == 4) {
            if (rem >= 2) { CP_WAIT2(); }
            else if (rem == 1) { CP_WAIT1(); }
            else { CP_WAIT0(); }
        } else {
            if (rem >= 1) { CP_WAIT1(); }
            else { CP_WAIT0(); }
        }
        __syncthreads();
        COMPUTE(st);
        if (kt + STG - 1 < nkt) FETCH(kt + STG - 1, (kt + STG - 1) % STG);
    }

    // Epilogue
    float* Cb = WF32 ? (C + (long long)bz * sC) : nullptr;
    __nv_bfloat16* Hh = WHI ? (Chi + (long long)bz * sC) : nullptr;
    __nv_bfloat16* Hl = WLO ? (Clo + (long long)bz * sC) : nullptr;
    const float* Rb = RESID ? (resid + (long long)bz * sC) : nullptr;

    const int r0 = lane >> 2;
    const int c0 = (lane & 3) * 2;
#pragma unroll
    for (int mt = 0; mt < MT; mt++) {
#pragma unroll
        for (int nt = 0; nt < 8; nt++) {
            const int col = n0 + wn + nt * 8 + c0;
#pragma unroll
            for (int h = 0; h < 2; h++) {
                const long long row = m0 + wm + mt * 16 + r0 + h * 8;
                float v0 = acc[mt][nt][h * 2 + 0] * alpha;
                float v1 = acc[mt][nt][h * 2 + 1] * alpha;
                if (BIAS)  { v0 += bias[col]; v1 += bias[col + 1]; }
                if (RESID) {
                    v0 += Rb[row * N + col];
                    v1 += Rb[row * N + col + 1];
                }
                if (WF32) {
                    float2 o = {v0, v1};
                    *reinterpret_cast<float2*>(&Cb[row * N + col]) = o;
                }
                if (WHI) {
                    __nv_bfloat16 h0 = __float2bfloat16(v0);
                    __nv_bfloat16 h1 = __float2bfloat16(v1);
                    __nv_bfloat162 hp; hp.x = h0; hp.y = h1;
                    *reinterpret_cast<__nv_bfloat162*>(&Hh[row * N + col]) = hp;
                    if (WLO) {
                        __nv_bfloat162 lp;
                        lp.x = __float2bfloat16(v0 - __bfloat162float(h0));
                        lp.y = __float2bfloat16(v1 - __bfloat162float(h1));
                        *reinterpret_cast<__nv_bfloat162*>(&Hl[row * N + col]) = lp;
                    }
                }
            }
        }
    }
}

// ---------------------------------------------------------------------------
// fp32 -> bf16 hi/lo split (vectorized by 4)
// ---------------------------------------------------------------------------
__global__ void __launch_bounds__(256)
split_kernel(const float* __restrict__ x, __nv_bfloat16* __restrict__ hi,
             __nv_bfloat16* __restrict__ lo, int n4) {
    const int i = blockIdx.x * 256 + threadIdx.x;
    if (i >= n4) return;
    const float4 v = reinterpret_cast<const float4*>(x)[i];
    __nv_bfloat16 h0 = __float2bfloat16(v.x), h1 = __float2bfloat16(v.y);
    __nv_bfloat16 h2 = __float2bfloat16(v.z), h3 = __float2bfloat16(v.w);
    __nv_bfloat162 hp0; hp0.x = h0; hp0.y = h1;
    __nv_bfloat162 hp1; hp1.x = h2; hp1.y = h3;
    __nv_bfloat162 lp0, lp1;
    lp0.x = __float2bfloat16(v.x - __bfloat162float(h0));
    lp0.y = __float2bfloat16(v.y - __bfloat162float(h1));
    lp1.x = __float2bfloat16(v.z - __bfloat162float(h2));
    lp1.y = __float2bfloat16(v.w - __bfloat162float(h3));
    reinterpret_cast<__nv_bfloat162*>(hi)[2 * i]     = hp0;
    reinterpret_cast<__nv_bfloat162*>(hi)[2 * i + 1] = hp1;
    reinterpret_cast<__nv_bfloat162*>(lo)[2 * i]     = lp0;
    reinterpret_cast<__nv_bfloat162*>(lo)[2 * i + 1] = lp1;
}

// ---------------------------------------------------------------------------
// Mask dtype probe (bool vs 4-byte): byte offset %4==1 nonzero => 1-byte bool
// ---------------------------------------------------------------------------
__global__ void detect_mask_kernel(const unsigned char* __restrict__ mask) {
    __shared__ int found;
    if (threadIdx.x == 0) found = 0;
    __syncthreads();
    for (int i = threadIdx.x; i < 1024; i += 256)
        if (mask[i * 4 + 1] != 0) found = 1;
    __syncthreads();
    if (threadIdx.x == 0) g_mask4 = found ? 0 : 1;
}

// ---------------------------------------------------------------------------
// Mask + softmax, in place on bf16 buffer: scores (bf16) -> probs (bf16)
// ---------------------------------------------------------------------------
__global__ void __launch_bounds__(256)
softmax_mask_kernel(__nv_bfloat16* __restrict__ p, const void* __restrict__ mask) {
    const long long row = blockIdx.x;
    __nv_bfloat16* pr = p + row * SS;
    const long long mbase = row * SS;
    const int tid = threadIdx.x;
    const int is4 = g_mask4;

    float vals[8];
    float mx = -3.0e38f;
#pragma unroll
    for (int i = 0; i < 8; i++) {
        const int c = tid + (i << 8);
        float x = __bfloat162float(pr[c]);
        bool m;
        if (is4) m = reinterpret_cast<const unsigned int*>(mask)[mbase + c] != 0u;
        else     m = reinterpret_cast<const unsigned char*>(mask)[mbase + c] != 0;
        x = m ? -1e9f : x;
        vals[i] = x;
        mx = fmaxf(mx, x);
    }
    __shared__ float sred[8];
#pragma unroll
    for (int o = 16; o > 0; o >>= 1) mx = fmaxf(mx, __shfl_xor_sync(0xffffffffu, mx, o));
    if ((tid & 31) == 0) sred[tid >> 5] = mx;
    __syncthreads();
    float bm = sred[0];
#pragma unroll
    for (int w = 1; w < 8; w++) bm = fmaxf(bm, sred[w]);

    float sum = 0.f;
#pragma unroll
    for (int i = 0; i < 8; i++) {
        const float e = __expf(vals[i] - bm);
        vals[i] = e;
        sum += e;
    }
#pragma unroll
    for (int o = 16; o > 0; o >>= 1) sum += __shfl_xor_sync(0xffffffffu, sum, o);
    __shared__ float ssum[8];
    if ((tid & 31) == 0) ssum[tid >> 5] = sum;
    __syncthreads();
    float ts = 0.f;
#pragma unroll
    for (int w = 0; w < 8; w++) ts += ssum[w];

    const float inv = 1.0f / ts;
#pragma unroll
    for (int i = 0; i < 8; i++) {
        const int c = tid + (i << 8);
        pr[c] = __float2bfloat16(vals[i] * inv);
    }
}

// ---------------------------------------------------------------------------
// kernel_launch
// ---------------------------------------------------------------------------
extern "C" void kernel_launch(void* const* d_in, const int* in_sizes, int n_in,
                              void* d_out, int out_size) {
    const float* Q    = (const float*)d_in[0];
    const float* Kin  = (const float*)d_in[1];
    const void*  mask = (const void*)d_in[2];
    const float* Wq   = (const float*)d_in[3];
    const float* Wk   = (const float*)d_in[4];
    const float* Wv   = (const float*)d_in[5];
    const float* Wp   = (const float*)d_in[6];
    const float* bp   = (const float*)d_in[7];
    float* out        = (float*)d_out;

    __nv_bfloat16 *Qhi, *Qlo, *Khi, *Klo, *Wqhi, *Wqlo, *Wkhi, *Wklo, *Wvhi, *Wvlo, *Wphi2, *Wplo2;
    __nv_bfloat16 *qhi, *khi, *vThi, *phi, *aohi;
    float *qf;
    cudaGetSymbolAddress((void**)&Qhi, g_Qhi);   cudaGetSymbolAddress((void**)&Qlo, g_Qlo);
    cudaGetSymbolAddress((void**)&Khi, g_Khi);   cudaGetSymbolAddress((void**)&Klo, g_Klo);
    cudaGetSymbolAddress((void**)&Wqhi, g_Wqhi); cudaGetSymbolAddress((void**)&Wqlo, g_Wqlo);
    cudaGetSymbolAddress((void**)&Wkhi, g_Wkhi); cudaGetSymbolAddress((void**)&Wklo, g_Wklo);
    cudaGetSymbolAddress((void**)&Wvhi, g_Wvhi); cudaGetSymbolAddress((void**)&Wvlo, g_Wvlo);
    cudaGetSymbolAddress((void**)&Wphi2, g_Wphi); cudaGetSymbolAddress((void**)&Wplo2, g_Wplo);
    cudaGetSymbolAddress((void**)&qf, g_qf);
    cudaGetSymbolAddress((void**)&qhi, g_qhi);
    cudaGetSymbolAddress((void**)&khi, g_khi);
    cudaGetSymbolAddress((void**)&vThi, g_vThi);
    cudaGetSymbolAddress((void**)&phi, g_phi);
    cudaGetSymbolAddress((void**)&aohi, g_aohi);

    constexpr int SM_1 = 4 * ((256 + 128) * PITCH);        // NPROD=1, BM=256, STG=4: 221184
    constexpr int SM_2 = 3 * ((256 + 256) * PITCH);        // NPROD=2, BM=256, STG=3: 221184
    constexpr int SM_3 = 3 * ((2 * 128 + 2 * 128) * PITCH);// NPROD=3, BM=128, STG=3: 221184
    cudaFuncSetAttribute(hmma_gemm<128, 3, 3, false, false, true,  true,  false>,
                         cudaFuncAttributeMaxDynamicSharedMemorySize, SM_3);
    cudaFuncSetAttribute(hmma_gemm<256, 3, 2, false, false, false, true,  false>,
                         cudaFuncAttributeMaxDynamicSharedMemorySize, SM_2);
    cudaFuncSetAttribute(hmma_gemm<256, 4, 1, false, false, false, true,  false>,
                         cudaFuncAttributeMaxDynamicSharedMemorySize, SM_1);
    cudaFuncSetAttribute(hmma_gemm<256, 3, 2, true,  true,  true,  false, false>,
                         cudaFuncAttributeMaxDynamicSharedMemorySize, SM_2);

    const float scale = 0.04419417382415922f;  // 512^-0.5
    const long long sQKV = (long long)SS * EE;
    const long long sSC  = (long long)SS * SS;
    dim3 blk(256);

    // 1) splits
    {
        const int nQ4 = MTOT * EE / 4, nW4 = EE * EE / 4;
        split_kernel<<<(nQ4 + 255) / 256, blk>>>(Q,   Qhi, Qlo, nQ4);
        split_kernel<<<(nQ4 + 255) / 256, blk>>>(Kin, Khi, Klo, nQ4);
        split_kernel<<<(nW4 + 255) / 256, blk>>>(Wq, Wqhi, Wqlo, nW4);
        split_kernel<<<(nW4 + 255) / 256, blk>>>(Wk, Wkhi, Wklo, nW4);
        split_kernel<<<(nW4 + 255) / 256, blk>>>(Wv, Wvhi, Wvlo, nW4);
        split_kernel<<<(nW4 + 255) / 256, blk>>>(Wp, Wphi2, Wplo2, nW4);
    }
    detect_mask_kernel<<<1, 256>>>((const unsigned char*)mask);

    // 2) q = Q Wq^T  (3-product; residual-critical) -> qf fp32 + qhi
    hmma_gemm<128, 3, 3, false, false, true, true, false>
        <<<dim3(EE / 128, MTOT / 128, 1), blk, SM_3>>>(
        Qhi, Qlo, Wqhi, Wqlo, qf, qhi, nullptr, MTOT, EE, EE, 0, 0, 0, 1.f, nullptr, nullptr);
    // 3) k = K Wk^T  (2-product) -> khi
    hmma_gemm<256, 3, 2, false, false, false, true, false>
        <<<dim3(EE / 128, MTOT / 256, 1), blk, SM_2>>>(
        Khi, nullptr, Wkhi, Wklo, nullptr, khi, nullptr, MTOT, EE, EE, 0, 0, 0, 1.f, nullptr, nullptr);
    // 4) vT[b] = Wv K[b]^T  (2-product) -> vThi
    hmma_gemm<256, 3, 2, false, false, false, true, false>
        <<<dim3(SS / 128, EE / 256, BB), blk, SM_2>>>(
        Wvhi, nullptr, Khi, Klo, nullptr, vThi, nullptr, EE, SS, EE,
        0, sQKV, (long long)EE * SS, 1.f, nullptr, nullptr);
    // 5) scores[b] = scale * q[b] k[b]^T  (1-product) -> bf16 into phi
    hmma_gemm<256, 4, 1, false, false, false, true, false>
        <<<dim3(SS / 128, SS / 256, BB), blk, SM_1>>>(
        qhi, nullptr, khi, nullptr, nullptr, phi, nullptr, SS, SS, EE,
        sQKV, sQKV, sSC, scale, nullptr, nullptr);
    // 6) mask + softmax in place on phi
    softmax_mask_kernel<<<BB * SS, blk>>>(phi, mask);
    // 7) ao[b] = p[b] vT[b]^T  (1-product) -> aohi
    hmma_gemm<256, 4, 1, false, false, false, true, false>
        <<<dim3(EE / 128, SS / 256, BB), blk, SM_1>>>(
        phi, nullptr, vThi, nullptr, nullptr, aohi, nullptr, SS, EE, SS,
        sSC, (long long)EE * SS, sQKV, 1.f, nullptr, nullptr);
    // 8) out = ao Wp^T + bp + q  (2-product)
    hmma_gemm<256, 3, 2, true, true, true, false, false>
        <<<dim3(EE / 128, MTOT / 256, 1), blk, SM_2>>>(
        aohi, nullptr, Wphi2, Wplo2, out, nullptr, nullptr, MTOT, EE, EE,
        0, 0, 0, 1.f, bp, qf);
}

// round 7
// speedup vs baseline: 7.2876x; 1.1256x over previous
#include <cuda_runtime.h>
#include <cuda_bf16.h>
#include <cstdint>

#define BB 8
#define SS 2048
#define EE 512
#define MTOT (BB * SS)

// ---------------------------------------------------------------------------
// Scratch (__device__ globals; no allocation anywhere)
// ---------------------------------------------------------------------------
__device__ __nv_bfloat16 g_Qhi[(size_t)MTOT * EE], g_Qlo[(size_t)MTOT * EE];
__device__ __nv_bfloat16 g_Khi[(size_t)MTOT * EE];
__device__ __nv_bfloat16 g_Wqhi[EE * EE], g_Wqlo[EE * EE];
__device__ __nv_bfloat16 g_Wkhi[EE * EE];
__device__ __nv_bfloat16 g_Wvhi[EE * EE];
__device__ __nv_bfloat16 g_Wphi[EE * EE];
__device__ float         g_qf [(size_t)MTOT * EE];
__device__ __nv_bfloat16 g_qhi[(size_t)MTOT * EE];
__device__ __nv_bfloat16 g_khi[(size_t)MTOT * EE];
__device__ __nv_bfloat16 g_vThi[(size_t)BB * EE * SS];
__device__ __nv_bfloat16 g_phi[(size_t)BB * SS * SS];   // scores (bf16) -> probs in place
__device__ __nv_bfloat16 g_aohi[(size_t)MTOT * EE];
__device__ int           g_mask4;

// ---------------------------------------------------------------------------
// Helpers (baseline PTX only; legal at .target sm_103)
// ---------------------------------------------------------------------------
__device__ __forceinline__ uint32_t smem_u32(const void* p) {
    uint32_t a;
    asm("{ .reg .u64 t; cvta.to.shared.u64 t, %1; cvt.u32.u64 %0, t; }"
        : "=r"(a) : "l"(p));
    return a;
}
__device__ __forceinline__ void cpasync16(uint32_t dst, const void* src) {
    asm volatile("cp.async.cg.shared.global [%0], [%1], 16;"
                 :: "r"(dst), "l"(src) : "memory");
}
#define CP_COMMIT() asm volatile("cp.async.commit_group;" ::: "memory")
#define CP_WAIT2()  asm volatile("cp.async.wait_group 2;" ::: "memory")
#define CP_WAIT1()  asm volatile("cp.async.wait_group 1;" ::: "memory")
#define CP_WAIT0()  asm volatile("cp.async.wait_group 0;" ::: "memory")

__device__ __forceinline__ void ldsm4(uint32_t* r, uint32_t addr) {
    asm volatile("ldmatrix.sync.aligned.m8n8.x4.shared.b16 {%0,%1,%2,%3}, [%4];"
                 : "=r"(r[0]), "=r"(r[1]), "=r"(r[2]), "=r"(r[3]) : "r"(addr));
}
__device__ __forceinline__ void mma_bf16(float* d, const uint32_t* a, const uint32_t* b) {
    asm volatile(
        "mma.sync.aligned.m16n8k16.row.col.f32.bf16.bf16.f32 "
        "{%0,%1,%2,%3}, {%4,%5,%6,%7}, {%8,%9}, {%0,%1,%2,%3};"
        : "+f"(d[0]), "+f"(d[1]), "+f"(d[2]), "+f"(d[3])
        : "r"(a[0]), "r"(a[1]), "r"(a[2]), "r"(a[3]), "r"(b[0]), "r"(b[1]));
}

// SMEM rows: 64 bf16 (128 B data), pitch 144 B => conflict-free ldmatrix
#define PITCH    144
#define BTILE_B  (128 * PITCH)          // B tile is always 128 rows

// ---------------------------------------------------------------------------
// HMMA NT GEMM: C[M,N] = alpha * A[M,K] * B[N,K]^T, bf16, fp32 acc.
// NPROD=1: Ah*Bh.  NPROD=2: Ah*Bh + Ah*Bl.  NPROD=3: + Al*Bh.
// Block BMx128, BK=64, 256 threads (8 warps: 4 m x 2 n, warp tile (BM/4)x64).
// STG-stage cp.async pipeline, one __syncthreads per K-iter.
// Requires M%BM==0, N%128==0, K%64==0, nkt>=STG.
// ---------------------------------------------------------------------------
template <int BM, int STG, int NPROD, bool BIAS, bool RESID, bool WF32, bool WHI, bool WLO>
__global__ void __launch_bounds__(256, 1)
hmma_gemm(const __nv_bfloat16* __restrict__ Ahi, const __nv_bfloat16* __restrict__ Alo,
          const __nv_bfloat16* __restrict__ Bhi, const __nv_bfloat16* __restrict__ Blo,
          float* __restrict__ C, __nv_bfloat16* __restrict__ Chi,
          __nv_bfloat16* __restrict__ Clo,
          int M, int N, int K,
          long long sA, long long sB, long long sC,
          float alpha, const float* __restrict__ bias, const float* __restrict__ resid) {
    constexpr int MT      = BM / 64;             // m16 tiles per warp
    constexpr uint32_t ATILE = (uint32_t)BM * PITCH;
    constexpr uint32_t OFF_AL = ATILE;                                // NPROD==3
    constexpr uint32_t OFF_BH = (NPROD == 3) ? 2u * ATILE : ATILE;
    constexpr uint32_t OFF_BL = OFF_BH + BTILE_B;                     // NPROD>=2
    constexpr uint32_t STAGE_B =
        ((NPROD == 3) ? 2u : 1u) * ATILE + ((NPROD >= 2) ? 2u : 1u) * BTILE_B;

    extern __shared__ __align__(128) char smem[];
    const uint32_t sb = smem_u32(smem);

    const int tid  = threadIdx.x;
    const int wid  = tid >> 5;
    const int lane = tid & 31;
    const int bz   = blockIdx.z;
    const int m0   = blockIdx.y * BM;
    const int n0   = blockIdx.x * 128;

    const __nv_bfloat16* Ah = Ahi + (long long)bz * sA;
    const __nv_bfloat16* Al = (NPROD == 3) ? (Alo + (long long)bz * sA) : nullptr;
    const __nv_bfloat16* Bh = Bhi + (long long)bz * sB;
    const __nv_bfloat16* Bl = (NPROD >= 2) ? (Blo + (long long)bz * sB) : nullptr;

    const int nkt = K >> 6;

    auto FETCH = [&](int kt, int st) {
        const uint32_t base = sb + (uint32_t)st * STAGE_B;
#pragma unroll
        for (int t = 0; t < BM / 32; t++) {
            const int c   = tid + t * 256;
            const int row = c >> 3;
            const int cp  = c & 7;
            const uint32_t doff = row * PITCH + cp * 16;
            const long long ga = (long long)(m0 + row) * K + (kt << 6) + cp * 8;
            cpasync16(base + doff, Ah + ga);
            if (NPROD == 3) cpasync16(base + OFF_AL + doff, Al + ga);
        }
#pragma unroll
        for (int t = 0; t < 4; t++) {
            const int c   = tid + t * 256;
            const int row = c >> 3;
            const int cp  = c & 7;
            const uint32_t doff = row * PITCH + cp * 16;
            const long long gb = (long long)(n0 + row) * K + (kt << 6) + cp * 8;
            cpasync16(base + OFF_BH + doff, Bh + gb);
            if (NPROD >= 2) cpasync16(base + OFF_BL + doff, Bl + gb);
        }
        CP_COMMIT();
    };

    float acc[MT][8][4];
#pragma unroll
    for (int mt = 0; mt < MT; mt++)
#pragma unroll
        for (int nt = 0; nt < 8; nt++)
#pragma unroll
            for (int j = 0; j < 4; j++) acc[mt][nt][j] = 0.f;

    const int wm = (wid & 3) * (BM / 4);   // warp m offset
    const int wn = (wid >> 2) * 64;        // warp n offset
    const int i8 = lane & 7;
    const uint32_t a_off = (uint32_t)(i8 + ((lane >> 3) & 1) * 8) * PITCH + (lane >> 4) * 16;
    const uint32_t b_off = (uint32_t)(i8 + ((lane >> 4) & 1) * 8) * PITCH + ((lane >> 3) & 1) * 16;

    auto COMPUTE = [&](int st) {
        const uint32_t base = sb + (uint32_t)st * STAGE_B;
        const uint32_t aAh = base + (uint32_t)wm * PITCH + a_off;
        const uint32_t aBh = base + OFF_BH + (uint32_t)wn * PITCH + b_off;
        const uint32_t aBl = base + OFF_BL + (uint32_t)wn * PITCH + b_off;
#pragma unroll
        for (int ks = 0; ks < 4; ks++) {
            uint32_t ah[MT][4], al[MT][4], bh[4][4], bl[4][4];
#pragma unroll
            for (int mt = 0; mt < MT; mt++) {
                ldsm4(ah[mt], aAh + mt * 16 * PITCH + ks * 32);
                if (NPROD == 3) ldsm4(al[mt], aAh + OFF_AL + mt * 16 * PITCH + ks * 32);
            }
#pragma unroll
            for (int nt = 0; nt < 4; nt++) {
                ldsm4(bh[nt], aBh + nt * 16 * PITCH + ks * 32);
                if (NPROD >= 2) ldsm4(bl[nt], aBl + nt * 16 * PITCH + ks * 32);
            }
#pragma unroll
            for (int mt = 0; mt < MT; mt++)
#pragma unroll
                for (int nt = 0; nt < 8; nt++)
                    mma_bf16(acc[mt][nt], ah[mt], &bh[nt >> 1][(nt & 1) * 2]);
            if (NPROD >= 2) {
#pragma unroll
                for (int mt = 0; mt < MT; mt++)
#pragma unroll
                    for (int nt = 0; nt < 8; nt++)
                        mma_bf16(acc[mt][nt], ah[mt], &bl[nt >> 1][(nt & 1) * 2]);
            }
            if (NPROD == 3) {
#pragma unroll
                for (int mt = 0; mt < MT; mt++)
#pragma unroll
                    for (int nt = 0; nt < 8; nt++)
                        mma_bf16(acc[mt][nt], al[mt], &bh[nt >> 1][(nt & 1) * 2]);
            }
        }
    };

    FETCH(0, 0);
    FETCH(1, 1);
    if (STG == 4) FETCH(2, 2);

    for (int kt = 0; kt < nkt; kt++) {
        const int st  = kt % STG;
        const int rem = nkt - kt - 1;
        if (STG == 4) {
            if (rem >= 2) { CP_WAIT2(); }
            else if (rem == 1) { CP_WAIT1(); }
            else { CP_WAIT0(); }
        } else {
            if (rem >= 1) { CP_WAIT1(); }
            else { CP_WAIT0(); }
        }
        __syncthreads();
        COMPUTE(st);
        if (kt + STG - 1 < nkt) FETCH(kt + STG - 1, (kt + STG - 1) % STG);
    }

    // Epilogue
    float* Cb = WF32 ? (C + (long long)bz * sC) : nullptr;
    __nv_bfloat16* Hh = WHI ? (Chi + (long long)bz * sC) : nullptr;
    __nv_bfloat16* Hl = WLO ? (Clo + (long long)bz * sC) : nullptr;
    const float* Rb = RESID ? (resid + (long long)bz * sC) : nullptr;

    const int r0 = lane >> 2;
    const int c0 = (lane & 3) * 2;
#pragma unroll
    for (int mt = 0; mt < MT; mt++) {
#pragma unroll
        for (int nt = 0; nt < 8; nt++) {
            const int col = n0 + wn + nt * 8 + c0;
#pragma unroll
            for (int h = 0; h < 2; h++) {
                const long long row = m0 + wm + mt * 16 + r0 + h * 8;
                float v0 = acc[mt][nt][h * 2 + 0] * alpha;
                float v1 = acc[mt][nt][h * 2 + 1] * alpha;
                if (BIAS)  { v0 += bias[col]; v1 += bias[col + 1]; }
                if (RESID) {
                    v0 += Rb[row * N + col];
                    v1 += Rb[row * N + col + 1];
                }
                if (WF32) {
                    float2 o = {v0, v1};
                    *reinterpret_cast<float2*>(&Cb[row * N + col]) = o;
                }
                if (WHI) {
                    __nv_bfloat16 h0 = __float2bfloat16(v0);
                    __nv_bfloat16 h1 = __float2bfloat16(v1);
                    __nv_bfloat162 hp; hp.x = h0; hp.y = h1;
                    *reinterpret_cast<__nv_bfloat162*>(&Hh[row * N + col]) = hp;
                    if (WLO) {
                        __nv_bfloat162 lp;
                        lp.x = __float2bfloat16(v0 - __bfloat162float(h0));
                        lp.y = __float2bfloat16(v1 - __bfloat162float(h1));
                        *reinterpret_cast<__nv_bfloat162*>(&Hl[row * N + col]) = lp;
                    }
                }
            }
        }
    }
}

// ---------------------------------------------------------------------------
// fp32 -> bf16 splits
// ---------------------------------------------------------------------------
__global__ void __launch_bounds__(256)
split_hilo_kernel(const float* __restrict__ x, __nv_bfloat16* __restrict__ hi,
                  __nv_bfloat16* __restrict__ lo, int n4) {
    const int i = blockIdx.x * 256 + threadIdx.x;
    if (i >= n4) return;
    const float4 v = reinterpret_cast<const float4*>(x)[i];
    __nv_bfloat16 h0 = __float2bfloat16(v.x), h1 = __float2bfloat16(v.y);
    __nv_bfloat16 h2 = __float2bfloat16(v.z), h3 = __float2bfloat16(v.w);
    __nv_bfloat162 hp0; hp0.x = h0; hp0.y = h1;
    __nv_bfloat162 hp1; hp1.x = h2; hp1.y = h3;
    __nv_bfloat162 lp0, lp1;
    lp0.x = __float2bfloat16(v.x - __bfloat162float(h0));
    lp0.y = __float2bfloat16(v.y - __bfloat162float(h1));
    lp1.x = __float2bfloat16(v.z - __bfloat162float(h2));
    lp1.y = __float2bfloat16(v.w - __bfloat162float(h3));
    reinterpret_cast<__nv_bfloat162*>(hi)[2 * i]     = hp0;
    reinterpret_cast<__nv_bfloat162*>(hi)[2 * i + 1] = hp1;
    reinterpret_cast<__nv_bfloat162*>(lo)[2 * i]     = lp0;
    reinterpret_cast<__nv_bfloat162*>(lo)[2 * i + 1] = lp1;
}

__global__ void __launch_bounds__(256)
split_hi_kernel(const float* __restrict__ x, __nv_bfloat16* __restrict__ hi, int n4) {
    const int i = blockIdx.x * 256 + threadIdx.x;
    if (i >= n4) return;
    const float4 v = reinterpret_cast<const float4*>(x)[i];
    __nv_bfloat162 hp0, hp1;
    hp0.x = __float2bfloat16(v.x); hp0.y = __float2bfloat16(v.y);
    hp1.x = __float2bfloat16(v.z); hp1.y = __float2bfloat16(v.w);
    reinterpret_cast<__nv_bfloat162*>(hi)[2 * i]     = hp0;
    reinterpret_cast<__nv_bfloat162*>(hi)[2 * i + 1] = hp1;
}

// ---------------------------------------------------------------------------
// Mask dtype probe (bool vs 4-byte): byte offset %4==1 nonzero => 1-byte bool
// ---------------------------------------------------------------------------
__global__ void detect_mask_kernel(const unsigned char* __restrict__ mask) {
    __shared__ int found;
    if (threadIdx.x == 0) found = 0;
    __syncthreads();
    for (int i = threadIdx.x; i < 1024; i += 256)
        if (mask[i * 4 + 1] != 0) found = 1;
    __syncthreads();
    if (threadIdx.x == 0) g_mask4 = found ? 0 : 1;
}

// ---------------------------------------------------------------------------
// Mask + softmax, in place on bf16 buffer
// ---------------------------------------------------------------------------
__global__ void __launch_bounds__(256)
softmax_mask_kernel(__nv_bfloat16* __restrict__ p, const void* __restrict__ mask) {
    const long long row = blockIdx.x;
    __nv_bfloat16* pr = p + row * SS;
    const long long mbase = row * SS;
    const int tid = threadIdx.x;
    const int is4 = g_mask4;

    float vals[8];
    float mx = -3.0e38f;
#pragma unroll
    for (int i = 0; i < 8; i++) {
        const int c = tid + (i << 8);
        float x = __bfloat162float(pr[c]);
        bool m;
        if (is4) m = reinterpret_cast<const unsigned int*>(mask)[mbase + c] != 0u;
        else     m = reinterpret_cast<const unsigned char*>(mask)[mbase + c] != 0;
        x = m ? -1e9f : x;
        vals[i] = x;
        mx = fmaxf(mx, x);
    }
    __shared__ float sred[8];
#pragma unroll
    for (int o = 16; o > 0; o >>= 1) mx = fmaxf(mx, __shfl_xor_sync(0xffffffffu, mx, o));
    if ((tid & 31) == 0) sred[tid >> 5] = mx;
    __syncthreads();
    float bm = sred[0];
#pragma unroll
    for (int w = 1; w < 8; w++) bm = fmaxf(bm, sred[w]);

    float sum = 0.f;
#pragma unroll
    for (int i = 0; i < 8; i++) {
        const float e = __expf(vals[i] - bm);
        vals[i] = e;
        sum += e;
    }
#pragma unroll
    for (int o = 16; o > 0; o >>= 1) sum += __shfl_xor_sync(0xffffffffu, sum, o);
    __shared__ float ssum[8];
    if ((tid & 31) == 0) ssum[tid >> 5] = sum;
    __syncthreads();
    float ts = 0.f;
#pragma unroll
    for (int w = 0; w < 8; w++) ts += ssum[w];

    const float inv = 1.0f / ts;
#pragma unroll
    for (int i = 0; i < 8; i++) {
        const int c = tid + (i << 8);
        pr[c] = __float2bfloat16(vals[i] * inv);
    }
}

// ---------------------------------------------------------------------------
// kernel_launch
// ---------------------------------------------------------------------------
extern "C" void kernel_launch(void* const* d_in, const int* in_sizes, int n_in,
                              void* d_out, int out_size) {
    const float* Q    = (const float*)d_in[0];
    const float* Kin  = (const float*)d_in[1];
    const void*  mask = (const void*)d_in[2];
    const float* Wq   = (const float*)d_in[3];
    const float* Wk   = (const float*)d_in[4];
    const float* Wv   = (const float*)d_in[5];
    const float* Wp   = (const float*)d_in[6];
    const float* bp   = (const float*)d_in[7];
    float* out        = (float*)d_out;

    __nv_bfloat16 *Qhi, *Qlo, *Khi, *Wqhi, *Wqlo, *Wkhi, *Wvhi, *Wphi2;
    __nv_bfloat16 *qhi, *khi, *vThi, *phi, *aohi;
    float *qf;
    cudaGetSymbolAddress((void**)&Qhi, g_Qhi);   cudaGetSymbolAddress((void**)&Qlo, g_Qlo);
    cudaGetSymbolAddress((void**)&Khi, g_Khi);
    cudaGetSymbolAddress((void**)&Wqhi, g_Wqhi); cudaGetSymbolAddress((void**)&Wqlo, g_Wqlo);
    cudaGetSymbolAddress((void**)&Wkhi, g_Wkhi);
    cudaGetSymbolAddress((void**)&Wvhi, g_Wvhi);
    cudaGetSymbolAddress((void**)&Wphi2, g_Wphi);
    cudaGetSymbolAddress((void**)&qf, g_qf);
    cudaGetSymbolAddress((void**)&qhi, g_qhi);
    cudaGetSymbolAddress((void**)&khi, g_khi);
    cudaGetSymbolAddress((void**)&vThi, g_vThi);
    cudaGetSymbolAddress((void**)&phi, g_phi);
    cudaGetSymbolAddress((void**)&aohi, g_aohi);

    constexpr int SM_1 = 4 * ((256 + 128) * PITCH);         // NPROD=1, BM=256, STG=4
    constexpr int SM_3 = 3 * ((2 * 128 + 2 * 128) * PITCH); // NPROD=3, BM=128, STG=3
    cudaFuncSetAttribute(hmma_gemm<128, 3, 3, false, false, true,  true,  false>,
                         cudaFuncAttributeMaxDynamicSharedMemorySize, SM_3);
    cudaFuncSetAttribute(hmma_gemm<256, 4, 1, false, false, false, true,  false>,
                         cudaFuncAttributeMaxDynamicSharedMemorySize, SM_1);
    cudaFuncSetAttribute(hmma_gemm<256, 4, 1, true,  true,  true,  false, false>,
                         cudaFuncAttributeMaxDynamicSharedMemorySize, SM_1);

    const float scale = 0.04419417382415922f;  // 512^-0.5
    const long long sQKV = (long long)SS * EE;
    const long long sSC  = (long long)SS * SS;
    dim3 blk(256);
    const int nQ4 = MTOT * EE / 4, nW4 = EE * EE / 4;

    // Launches 1-5: splits + probe (ordered so launch 6 is a GEMM for ncu)
    split_hilo_kernel<<<(nQ4 + 255) / 256, blk>>>(Q, Qhi, Qlo, nQ4);         // 1
    split_hi_kernel<<<(nQ4 + 255) / 256, blk>>>(Kin, Khi, nQ4);              // 2
    split_hilo_kernel<<<(nW4 + 255) / 256, blk>>>(Wq, Wqhi, Wqlo, nW4);      // 3
    split_hi_kernel<<<(nW4 + 255) / 256, blk>>>(Wk, Wkhi, nW4);              // 4
    detect_mask_kernel<<<1, 256>>>((const unsigned char*)mask);              // 5

    // 6: k = K Wk^T  (1-product) -> khi   [ncu capture target]
    hmma_gemm<256, 4, 1, false, false, false, true, false>
        <<<dim3(EE / 128, MTOT / 256, 1), blk, SM_1>>>(
        Khi, nullptr, Wkhi, nullptr, nullptr, khi, nullptr, MTOT, EE, EE,
        0, 0, 0, 1.f, nullptr, nullptr);

    // 7-8: remaining splits
    split_hi_kernel<<<(nW4 + 255) / 256, blk>>>(Wv, Wvhi, nW4);              // 7
    split_hi_kernel<<<(nW4 + 255) / 256, blk>>>(Wp, Wphi2, nW4);             // 8

    // 9: q = Q Wq^T  (3-product; residual-critical) -> qf fp32 + qhi
    hmma_gemm<128, 3, 3, false, false, true, true, false>
        <<<dim3(EE / 128, MTOT / 128, 1), blk, SM_3>>>(
        Qhi, Qlo, Wqhi, Wqlo, qf, qhi, nullptr, MTOT, EE, EE, 0, 0, 0, 1.f, nullptr, nullptr);
    // 10: vT[b] = Wv K[b]^T  (1-product) -> vThi
    hmma_gemm<256, 4, 1, false, false, false, true, false>
        <<<dim3(SS / 128, EE / 256, BB), blk, SM_1>>>(
        Wvhi, nullptr, Khi, nullptr, nullptr, vThi, nullptr, EE, SS, EE,
        0, sQKV, (long long)EE * SS, 1.f, nullptr, nullptr);
    // 11: scores[b] = scale * q[b] k[b]^T  (1-product) -> bf16 into phi
    hmma_gemm<256, 4, 1, false, false, false, true, false>
        <<<dim3(SS / 128, SS / 256, BB), blk, SM_1>>>(
        qhi, nullptr, khi, nullptr, nullptr, phi, nullptr, SS, SS, EE,
        sQKV, sQKV, sSC, scale, nullptr, nullptr);
    // 12: mask + softmax in place on phi
    softmax_mask_kernel<<<BB * SS, blk>>>(phi, mask);
    // 13: ao[b] = p[b] vT[b]^T  (1-product) -> aohi
    hmma_gemm<256, 4, 1, false, false, false, true, false>
        <<<dim3(EE / 128, SS / 256, BB), blk, SM_1>>>(
        phi, nullptr, vThi, nullptr, nullptr, aohi, nullptr, SS, EE, SS,
        sSC, (long long)EE * SS, sQKV, 1.f, nullptr, nullptr);
    // 14: out = ao Wp^T + bp + q  (1-product + bias + residual)
    hmma_gemm<256, 4, 1, true, true, true, false, false>
        <<<dim3(EE / 128, MTOT / 256, 1), blk, SM_1>>>(
        aohi, nullptr, Wphi2, nullptr, out, nullptr, nullptr, MTOT, EE, EE,
        0, 0, 0, 1.f, bp, qf);
}

// round 8
// speedup vs baseline: 7.4866x; 1.0273x over previous
#include <cuda_runtime.h>
#include <cuda_bf16.h>
#include <cstdint>

#define BB 8
#define SS 2048
#define EE 512
#define MTOT (BB * SS)

// ---------------------------------------------------------------------------
// Scratch (__device__ globals; no allocation anywhere)
// ---------------------------------------------------------------------------
__device__ __nv_bfloat16 g_Qhi[(size_t)MTOT * EE], g_Qlo[(size_t)MTOT * EE];
__device__ __nv_bfloat16 g_Khi[(size_t)MTOT * EE];
__device__ __nv_bfloat16 g_Wqhi[EE * EE], g_Wqlo[EE * EE];
__device__ __nv_bfloat16 g_Wkhi[EE * EE];
__device__ __nv_bfloat16 g_Wvhi[EE * EE];
__device__ __nv_bfloat16 g_Wphi[EE * EE];
__device__ float         g_qf [(size_t)MTOT * EE];
__device__ __nv_bfloat16 g_qhi[(size_t)MTOT * EE];
__device__ __nv_bfloat16 g_khi[(size_t)MTOT * EE];
__device__ __nv_bfloat16 g_vThi[(size_t)BB * EE * SS];
__device__ __nv_bfloat16 g_phi[(size_t)BB * SS * SS];   // scores (bf16) -> probs in place
__device__ __nv_bfloat16 g_aohi[(size_t)MTOT * EE];
__device__ int           g_mask4;

// ---------------------------------------------------------------------------
// Helpers (baseline PTX only; legal at .target sm_103)
// ---------------------------------------------------------------------------
__device__ __forceinline__ uint32_t smem_u32(const void* p) {
    uint32_t a;
    asm("{ .reg .u64 t; cvta.to.shared.u64 t, %1; cvt.u32.u64 %0, t; }"
        : "=r"(a) : "l"(p));
    return a;
}
__device__ __forceinline__ void cpasync16(uint32_t dst, const void* src) {
    asm volatile("cp.async.cg.shared.global [%0], [%1], 16;"
                 :: "r"(dst), "l"(src) : "memory");
}
#define CP_COMMIT() asm volatile("cp.async.commit_group;" ::: "memory")
#define CP_WAIT2()  asm volatile("cp.async.wait_group 2;" ::: "memory")
#define CP_WAIT1()  asm volatile("cp.async.wait_group 1;" ::: "memory")
#define CP_WAIT0()  asm volatile("cp.async.wait_group 0;" ::: "memory")

__device__ __forceinline__ void ldsm4(uint32_t* r, uint32_t addr) {
    asm volatile("ldmatrix.sync.aligned.m8n8.x4.shared.b16 {%0,%1,%2,%3}, [%4];"
                 : "=r"(r[0]), "=r"(r[1]), "=r"(r[2]), "=r"(r[3]) : "r"(addr));
}
__device__ __forceinline__ void mma_bf16(float* d, const uint32_t* a, const uint32_t* b) {
    asm volatile(
        "mma.sync.aligned.m16n8k16.row.col.f32.bf16.bf16.f32 "
        "{%0,%1,%2,%3}, {%4,%5,%6,%7}, {%8,%9}, {%0,%1,%2,%3};"
        : "+f"(d[0]), "+f"(d[1]), "+f"(d[2]), "+f"(d[3])
        : "r"(a[0]), "r"(a[1]), "r"(a[2]), "r"(a[3]), "r"(b[0]), "r"(b[1]));
}

// SMEM rows: 64 bf16 (128 B data), pitch 144 B => conflict-free ldmatrix
#define PITCH    144
#define BTILE_B  (128 * PITCH)          // B tile is always 128 rows

// ---------------------------------------------------------------------------
// HMMA NT GEMM: C[M,N] = alpha * A[M,K] * B[N,K]^T, bf16, fp32 acc.
// NPROD=1: Ah*Bh.  NPROD=3: Ah*Bh + Ah*Bl + Al*Bh.
// Block BMx128, BK=64, 256 threads (8 warps: 4 m x 2 n), OCC CTAs/SM.
// STG-stage cp.async pipeline, one __syncthreads per K-iter.
// Requires M%BM==0, N%128==0, K%64==0, nkt>=STG.
// ---------------------------------------------------------------------------
template <int BM, int STG, int NPROD, int OCC,
          bool BIAS, bool RESID, bool WF32, bool WHI>
__global__ void __launch_bounds__(256, OCC)
hmma_gemm(const __nv_bfloat16* __restrict__ Ahi, const __nv_bfloat16* __restrict__ Alo,
          const __nv_bfloat16* __restrict__ Bhi, const __nv_bfloat16* __restrict__ Blo,
          float* __restrict__ C, __nv_bfloat16* __restrict__ Chi,
          int M, int N, int K,
          long long sA, long long sB, long long sC,
          float alpha, const float* __restrict__ bias, const float* __restrict__ resid) {
    constexpr int MT      = BM / 64;             // m16 tiles per warp
    constexpr uint32_t ATILE = (uint32_t)BM * PITCH;
    constexpr uint32_t OFF_AL = ATILE;                                // NPROD==3
    constexpr uint32_t OFF_BH = (NPROD == 3) ? 2u * ATILE : ATILE;
    constexpr uint32_t OFF_BL = OFF_BH + BTILE_B;                     // NPROD==3
    constexpr uint32_t STAGE_B =
        ((NPROD == 3) ? 2u : 1u) * ATILE + ((NPROD == 3) ? 2u : 1u) * BTILE_B;

    extern __shared__ __align__(128) char smem[];
    const uint32_t sb = smem_u32(smem);

    const int tid  = threadIdx.x;
    const int wid  = tid >> 5;
    const int lane = tid & 31;
    const int bz   = blockIdx.z;
    const int m0   = blockIdx.y * BM;
    const int n0   = blockIdx.x * 128;

    const __nv_bfloat16* Ah = Ahi + (long long)bz * sA;
    const __nv_bfloat16* Al = (NPROD == 3) ? (Alo + (long long)bz * sA) : nullptr;
    const __nv_bfloat16* Bh = Bhi + (long long)bz * sB;
    const __nv_bfloat16* Bl = (NPROD == 3) ? (Blo + (long long)bz * sB) : nullptr;

    const int nkt = K >> 6;

    auto FETCH = [&](int kt, int st) {
        const uint32_t base = sb + (uint32_t)st * STAGE_B;
#pragma unroll
        for (int t = 0; t < BM / 32; t++) {
            const int c   = tid + t * 256;
            const int row = c >> 3;
            const int cp  = c & 7;
            const uint32_t doff = row * PITCH + cp * 16;
            const long long ga = (long long)(m0 + row) * K + (kt << 6) + cp * 8;
            cpasync16(base + doff, Ah + ga);
            if (NPROD == 3) cpasync16(base + OFF_AL + doff, Al + ga);
        }
#pragma unroll
        for (int t = 0; t < 4; t++) {
            const int c   = tid + t * 256;
            const int row = c >> 3;
            const int cp  = c & 7;
            const uint32_t doff = row * PITCH + cp * 16;
            const long long gb = (long long)(n0 + row) * K + (kt << 6) + cp * 8;
            cpasync16(base + OFF_BH + doff, Bh + gb);
            if (NPROD == 3) cpasync16(base + OFF_BL + doff, Bl + gb);
        }
        CP_COMMIT();
    };

    float acc[MT][8][4];
#pragma unroll
    for (int mt = 0; mt < MT; mt++)
#pragma unroll
        for (int nt = 0; nt < 8; nt++)
#pragma unroll
            for (int j = 0; j < 4; j++) acc[mt][nt][j] = 0.f;

    const int wm = (wid & 3) * (BM / 4);   // warp m offset
    const int wn = (wid >> 2) * 64;        // warp n offset
    const int i8 = lane & 7;
    const uint32_t a_off = (uint32_t)(i8 + ((lane >> 3) & 1) * 8) * PITCH + (lane >> 4) * 16;
    const uint32_t b_off = (uint32_t)(i8 + ((lane >> 4) & 1) * 8) * PITCH + ((lane >> 3) & 1) * 16;

    auto COMPUTE = [&](int st) {
        const uint32_t base = sb + (uint32_t)st * STAGE_B;
        const uint32_t aAh = base + (uint32_t)wm * PITCH + a_off;
        const uint32_t aBh = base + OFF_BH + (uint32_t)wn * PITCH + b_off;
        const uint32_t aBl = base + OFF_BL + (uint32_t)wn * PITCH + b_off;
#pragma unroll
        for (int ks = 0; ks < 4; ks++) {
            uint32_t ah[MT][4], al[MT][4], bh[4][4], bl[4][4];
#pragma unroll
            for (int mt = 0; mt < MT; mt++) {
                ldsm4(ah[mt], aAh + mt * 16 * PITCH + ks * 32);
                if (NPROD == 3) ldsm4(al[mt], aAh + OFF_AL + mt * 16 * PITCH + ks * 32);
            }
#pragma unroll
            for (int nt = 0; nt < 4; nt++) {
                ldsm4(bh[nt], aBh + nt * 16 * PITCH + ks * 32);
                if (NPROD == 3) ldsm4(bl[nt], aBl + nt * 16 * PITCH + ks * 32);
            }
#pragma unroll
            for (int mt = 0; mt < MT; mt++)
#pragma unroll
                for (int nt = 0; nt < 8; nt++)
                    mma_bf16(acc[mt][nt], ah[mt], &bh[nt >> 1][(nt & 1) * 2]);
            if (NPROD == 3) {
#pragma unroll
                for (int mt = 0; mt < MT; mt++)
#pragma unroll
                    for (int nt = 0; nt < 8; nt++)
                        mma_bf16(acc[mt][nt], ah[mt], &bl[nt >> 1][(nt & 1) * 2]);
#pragma unroll
                for (int mt = 0; mt < MT; mt++)
#pragma unroll
                    for (int nt = 0; nt < 8; nt++)
                        mma_bf16(acc[mt][nt], al[mt], &bh[nt >> 1][(nt & 1) * 2]);
            }
        }
    };

    FETCH(0, 0);
    FETCH(1, 1);
    if (STG == 4) FETCH(2, 2);

    for (int kt = 0; kt < nkt; kt++) {
        const int st  = kt % STG;
        const int rem = nkt - kt - 1;
        if (STG == 4) {
            if (rem >= 2) { CP_WAIT2(); }
            else if (rem == 1) { CP_WAIT1(); }
            else { CP_WAIT0(); }
        } else {
            if (rem >= 1) { CP_WAIT1(); }
            else { CP_WAIT0(); }
        }
        __syncthreads();
        COMPUTE(st);
        if (kt + STG - 1 < nkt) FETCH(kt + STG - 1, (kt + STG - 1) % STG);
    }

    // Epilogue
    float* Cb = WF32 ? (C + (long long)bz * sC) : nullptr;
    __nv_bfloat16* Hh = WHI ? (Chi + (long long)bz * sC) : nullptr;
    const float* Rb = RESID ? (resid + (long long)bz * sC) : nullptr;

    const int r0 = lane >> 2;
    const int c0 = (lane & 3) * 2;
#pragma unroll
    for (int mt = 0; mt < MT; mt++) {
#pragma unroll
        for (int nt = 0; nt < 8; nt++) {
            const int col = n0 + wn + nt * 8 + c0;
#pragma unroll
            for (int h = 0; h < 2; h++) {
                const long long row = m0 + wm + mt * 16 + r0 + h * 8;
                float v0 = acc[mt][nt][h * 2 + 0] * alpha;
                float v1 = acc[mt][nt][h * 2 + 1] * alpha;
                if (BIAS)  { v0 += bias[col]; v1 += bias[col + 1]; }
                if (RESID) {
                    v0 += Rb[row * N + col];
                    v1 += Rb[row * N + col + 1];
                }
                if (WF32) {
                    float2 o = {v0, v1};
                    *reinterpret_cast<float2*>(&Cb[row * N + col]) = o;
                }
                if (WHI) {
                    __nv_bfloat162 hp;
                    hp.x = __float2bfloat16(v0);
                    hp.y = __float2bfloat16(v1);
                    *reinterpret_cast<__nv_bfloat162*>(&Hh[row * N + col]) = hp;
                }
            }
        }
    }
}

// ---------------------------------------------------------------------------
// fp32 -> bf16 splits
// ---------------------------------------------------------------------------
__global__ void __launch_bounds__(256)
split_hilo_kernel(const float* __restrict__ x, __nv_bfloat16* __restrict__ hi,
                  __nv_bfloat16* __restrict__ lo, int n4) {
    const int i = blockIdx.x * 256 + threadIdx.x;
    if (i >= n4) return;
    const float4 v = reinterpret_cast<const float4*>(x)[i];
    __nv_bfloat16 h0 = __float2bfloat16(v.x), h1 = __float2bfloat16(v.y);
    __nv_bfloat16 h2 = __float2bfloat16(v.z), h3 = __float2bfloat16(v.w);
    __nv_bfloat162 hp0; hp0.x = h0; hp0.y = h1;
    __nv_bfloat162 hp1; hp1.x = h2; hp1.y = h3;
    __nv_bfloat162 lp0, lp1;
    lp0.x = __float2bfloat16(v.x - __bfloat162float(h0));
    lp0.y = __float2bfloat16(v.y - __bfloat162float(h1));
    lp1.x = __float2bfloat16(v.z - __bfloat162float(h2));
    lp1.y = __float2bfloat16(v.w - __bfloat162float(h3));
    reinterpret_cast<__nv_bfloat162*>(hi)[2 * i]     = hp0;
    reinterpret_cast<__nv_bfloat162*>(hi)[2 * i + 1] = hp1;
    reinterpret_cast<__nv_bfloat162*>(lo)[2 * i]     = lp0;
    reinterpret_cast<__nv_bfloat162*>(lo)[2 * i + 1] = lp1;
}

__global__ void __launch_bounds__(256)
split_hi_kernel(const float* __restrict__ x, __nv_bfloat16* __restrict__ hi, int n4) {
    const int i = blockIdx.x * 256 + threadIdx.x;
    if (i >= n4) return;
    const float4 v = reinterpret_cast<const float4*>(x)[i];
    __nv_bfloat162 hp0, hp1;
    hp0.x = __float2bfloat16(v.x); hp0.y = __float2bfloat16(v.y);
    hp1.x = __float2bfloat16(v.z); hp1.y = __float2bfloat16(v.w);
    reinterpret_cast<__nv_bfloat162*>(hi)[2 * i]     = hp0;
    reinterpret_cast<__nv_bfloat162*>(hi)[2 * i + 1] = hp1;
}

// ---------------------------------------------------------------------------
// Mask dtype probe (bool vs 4-byte): byte offset %4==1 nonzero => 1-byte bool
// ---------------------------------------------------------------------------
__global__ void detect_mask_kernel(const unsigned char* __restrict__ mask) {
    __shared__ int found;
    if (threadIdx.x == 0) found = 0;
    __syncthreads();
    for (int i = threadIdx.x; i < 1024; i += 256)
        if (mask[i * 4 + 1] != 0) found = 1;
    __syncthreads();
    if (threadIdx.x == 0) g_mask4 = found ? 0 : 1;
}

// ---------------------------------------------------------------------------
// Mask + softmax, in place on bf16 buffer
// ---------------------------------------------------------------------------
__global__ void __launch_bounds__(256)
softmax_mask_kernel(__nv_bfloat16* __restrict__ p, const void* __restrict__ mask) {
    const long long row = blockIdx.x;
    __nv_bfloat16* pr = p + row * SS;
    const long long mbase = row * SS;
    const int tid = threadIdx.x;
    const int is4 = g_mask4;

    float vals[8];
    float mx = -3.0e38f;
#pragma unroll
    for (int i = 0; i < 8; i++) {
        const int c = tid + (i << 8);
        float x = __bfloat162float(pr[c]);
        bool m;
        if (is4) m = reinterpret_cast<const unsigned int*>(mask)[mbase + c] != 0u;
        else     m = reinterpret_cast<const unsigned char*>(mask)[mbase + c] != 0;
        x = m ? -1e9f : x;
        vals[i] = x;
        mx = fmaxf(mx, x);
    }
    __shared__ float sred[8];
#pragma unroll
    for (int o = 16; o > 0; o >>= 1) mx = fmaxf(mx, __shfl_xor_sync(0xffffffffu, mx, o));
    if ((tid & 31) == 0) sred[tid >> 5] = mx;
    __syncthreads();
    float bm = sred[0];
#pragma unroll
    for (int w = 1; w < 8; w++) bm = fmaxf(bm, sred[w]);

    float sum = 0.f;
#pragma unroll
    for (int i = 0; i < 8; i++) {
        const float e = __expf(vals[i] - bm);
        vals[i] = e;
        sum += e;
    }
#pragma unroll
    for (int o = 16; o > 0; o >>= 1) sum += __shfl_xor_sync(0xffffffffu, sum, o);
    __shared__ float ssum[8];
    if ((tid & 31) == 0) ssum[tid >> 5] = sum;
    __syncthreads();
    float ts = 0.f;
#pragma unroll
    for (int w = 0; w < 8; w++) ts += ssum[w];

    const float inv = 1.0f / ts;
#pragma unroll
    for (int i = 0; i < 8; i++) {
        const int c = tid + (i << 8);
        pr[c] = __float2bfloat16(vals[i] * inv);
    }
}

// ---------------------------------------------------------------------------
// kernel_launch
// ---------------------------------------------------------------------------
extern "C" void kernel_launch(void* const* d_in, const int* in_sizes, int n_in,
                              void* d_out, int out_size) {
    const float* Q    = (const float*)d_in[0];
    const float* Kin  = (const float*)d_in[1];
    const void*  mask = (const void*)d_in[2];
    const float* Wq   = (const float*)d_in[3];
    const float* Wk   = (const float*)d_in[4];
    const float* Wv   = (const float*)d_in[5];
    const float* Wp   = (const float*)d_in[6];
    const float* bp   = (const float*)d_in[7];
    float* out        = (float*)d_out;

    __nv_bfloat16 *Qhi, *Qlo, *Khi, *Wqhi, *Wqlo, *Wkhi, *Wvhi, *Wphi2;
    __nv_bfloat16 *qhi, *khi, *vThi, *phi, *aohi;
    float *qf;
    cudaGetSymbolAddress((void**)&Qhi, g_Qhi);   cudaGetSymbolAddress((void**)&Qlo, g_Qlo);
    cudaGetSymbolAddress((void**)&Khi, g_Khi);
    cudaGetSymbolAddress((void**)&Wqhi, g_Wqhi); cudaGetSymbolAddress((void**)&Wqlo, g_Wqlo);
    cudaGetSymbolAddress((void**)&Wkhi, g_Wkhi);
    cudaGetSymbolAddress((void**)&Wvhi, g_Wvhi);
    cudaGetSymbolAddress((void**)&Wphi2, g_Wphi);
    cudaGetSymbolAddress((void**)&qf, g_qf);
    cudaGetSymbolAddress((void**)&qhi, g_qhi);
    cudaGetSymbolAddress((void**)&khi, g_khi);
    cudaGetSymbolAddress((void**)&vThi, g_vThi);
    cudaGetSymbolAddress((void**)&phi, g_phi);
    cudaGetSymbolAddress((void**)&aohi, g_aohi);

    // NPROD=1, BM=128, STG=3, 2 CTAs/SM: stage 36864, smem/CTA 110592
    constexpr int SM_1 = 3 * ((128 + 128) * PITCH);
    // NPROD=3, BM=128, STG=3, 1 CTA/SM: smem 221184
    constexpr int SM_3 = 3 * ((2 * 128 + 2 * 128) * PITCH);
    cudaFuncSetAttribute(hmma_gemm<128, 3, 3, 1, false, false, true,  true >,
                         cudaFuncAttributeMaxDynamicSharedMemorySize, SM_3);
    cudaFuncSetAttribute(hmma_gemm<128, 3, 1, 2, false, false, false, true >,
                         cudaFuncAttributeMaxDynamicSharedMemorySize, SM_1);
    cudaFuncSetAttribute(hmma_gemm<128, 3, 1, 2, true,  true,  true,  false>,
                         cudaFuncAttributeMaxDynamicSharedMemorySize, SM_1);

    const float scale = 0.04419417382415922f;  // 512^-0.5
    const long long sQKV = (long long)SS * EE;
    const long long sSC  = (long long)SS * SS;
    dim3 blk(256);
    const int nQ4 = MTOT * EE / 4, nW4 = EE * EE / 4;

    // Splits + probe
    split_hilo_kernel<<<(nQ4 + 255) / 256, blk>>>(Q, Qhi, Qlo, nQ4);
    split_hi_kernel<<<(nQ4 + 255) / 256, blk>>>(Kin, Khi, nQ4);
    split_hilo_kernel<<<(nW4 + 255) / 256, blk>>>(Wq, Wqhi, Wqlo, nW4);
    split_hi_kernel<<<(nW4 + 255) / 256, blk>>>(Wk, Wkhi, nW4);
    split_hi_kernel<<<(nW4 + 255) / 256, blk>>>(Wv, Wvhi, nW4);
    split_hi_kernel<<<(nW4 + 255) / 256, blk>>>(Wp, Wphi2, nW4);
    detect_mask_kernel<<<1, 256>>>((const unsigned char*)mask);

    // q = Q Wq^T  (3-product; residual-critical) -> qf fp32 + qhi
    hmma_gemm<128, 3, 3, 1, false, false, true, true>
        <<<dim3(EE / 128, MTOT / 128, 1), blk, SM_3>>>(
        Qhi, Qlo, Wqhi, Wqlo, qf, qhi, MTOT, EE, EE, 0, 0, 0, 1.f, nullptr, nullptr);
    // k = K Wk^T  (1-product) -> khi
    hmma_gemm<128, 3, 1, 2, false, false, false, true>
        <<<dim3(EE / 128, MTOT / 128, 1), blk, SM_1>>>(
        Khi, nullptr, Wkhi, nullptr, nullptr, khi, MTOT, EE, EE,
        0, 0, 0, 1.f, nullptr, nullptr);
    // vT[b] = Wv K[b]^T  (1-product) -> vThi
    hmma_gemm<128, 3, 1, 2, false, false, false, true>
        <<<dim3(SS / 128, EE / 128, BB), blk, SM_1>>>(
        Wvhi, nullptr, Khi, nullptr, nullptr, vThi, EE, SS, EE,
        0, sQKV, (long long)EE * SS, 1.f, nullptr, nullptr);
    // scores[b] = scale * q[b] k[b]^T  (1-product) -> bf16 into phi
    hmma_gemm<128, 3, 1, 2, false, false, false, true>
        <<<dim3(SS / 128, SS / 128, BB), blk, SM_1>>>(
        qhi, nullptr, khi, nullptr, nullptr, phi, SS, SS, EE,
        sQKV, sQKV, sSC, scale, nullptr, nullptr);
    // mask + softmax in place on phi
    softmax_mask_kernel<<<BB * SS, blk>>>(phi, mask);
    // ao[b] = p[b] vT[b]^T  (1-product) -> aohi
    hmma_gemm<128, 3, 1, 2, false, false, false, true>
        <<<dim3(EE / 128, SS / 128, BB), blk, SM_1>>>(
        phi, nullptr, vThi, nullptr, nullptr, aohi, SS, EE, SS,
        sSC, (long long)EE * SS, sQKV, 1.f, nullptr, nullptr);
    // out = ao Wp^T + bp + q  (1-product + bias + residual)
    hmma_gemm<128, 3, 1, 2, true, true, true, false>
        <<<dim3(EE / 128, MTOT / 128, 1), blk, SM_1>>>(
        aohi, nullptr, Wphi2, nullptr, out, nullptr, MTOT, EE, EE,
        0, 0, 0, 1.f, bp, qf);
}